// round 8
// baseline (speedup 1.0000x reference)
#include <cuda_runtime.h>
#include <cuda_fp16.h>
#include <cuda_bf16.h>
#include <math.h>
#include <stdint.h>

#define B    2
#define T    2048
#define H    1024
#define NH   16
#define D    64
#define SCALE 0.125f   // D^-0.5

// ---------------- static device scratch (no dynamic allocation allowed) ----
__device__ __nv_bfloat16 g_Xh[(size_t)B * T * H];   // 8 MB  x in bf16
__device__ __nv_bfloat16 g_Wt[(size_t)2 * H * H];   // 4 MB  Wq/Wk bf16, [z][n][k]
__device__ __nv_bfloat16 g_Qh[(size_t)B * T * H];   // 8 MB
__device__ __nv_bfloat16 g_Kh[(size_t)B * T * H];   // 8 MB
__device__ float  g_Vp[(size_t)4 * B * T * D];      // 4 MB V split-K partials
__device__ float  g_V[(size_t)B * T * D];           // 1 MB
__device__ __half g_Wh[(size_t)NH * B * T * T];     // 268 MB exp(score) fp16
__device__ float  g_RS[(size_t)NH * B * T * 16];    // 4 MB per-(row,s-tile) exp sums
__device__ float  g_MHp[(size_t)8 * B * T * D];     // 8 MB AV partials (8 chunks)

// ======================= helpers ===========================================
__device__ __forceinline__ void mma_bf16(float* d, const uint32_t* a, const uint32_t* b) {
    asm volatile(
        "mma.sync.aligned.m16n8k16.row.col.f32.bf16.bf16.f32 "
        "{%0,%1,%2,%3}, {%4,%5,%6,%7}, {%8,%9}, {%0,%1,%2,%3};"
        : "+f"(d[0]), "+f"(d[1]), "+f"(d[2]), "+f"(d[3])
        : "r"(a[0]), "r"(a[1]), "r"(a[2]), "r"(a[3]), "r"(b[0]), "r"(b[1]));
}

// ======================= prep kernels ======================================
// x fp32 -> bf16. grid = B*T, block 256.
__global__ void xcast_kernel(const float* __restrict__ x)
{
    const int m = blockIdx.x;
    const float4 v = ((const float4*)(x + (size_t)m * H))[threadIdx.x];
    __nv_bfloat162* dst = (__nv_bfloat162*)(g_Xh + (size_t)m * H);
    dst[threadIdx.x * 2]     = __floats2bfloat162_rn(v.x, v.y);
    dst[threadIdx.x * 2 + 1] = __floats2bfloat162_rn(v.z, v.w);
}

// Wq/Wk [NH,H,D] -> g_Wt[z][n][k] bf16 (n = head*64+d, k = h).
// grid (32,32,2), block (32,8).
__global__ void wtrans_kernel(const float* __restrict__ Wq, const float* __restrict__ Wk)
{
    const float* Wsrc = blockIdx.z ? Wk : Wq;
    __nv_bfloat16* out = g_Wt + (size_t)blockIdx.z * H * H;
    __shared__ float tile[32][33];
    const int k0 = blockIdx.x * 32, n0 = blockIdx.y * 32;
    const int tx = threadIdx.x, ty = threadIdx.y;
#pragma unroll
    for (int j = 0; j < 4; j++) {
        const int k = k0 + ty + 8 * j;
        const int n = n0 + tx;
        tile[ty + 8 * j][tx] = Wsrc[(size_t)(n >> 6) * (H * D) + (size_t)k * D + (n & 63)];
    }
    __syncthreads();
#pragma unroll
    for (int j = 0; j < 4; j++) {
        const int n = n0 + ty + 8 * j;
        out[(size_t)n * H + k0 + tx] = __float2bfloat16(tile[tx][ty + 8 * j]);
    }
}

// ======================= Kernel 1: Q/K projection (bf16 mma.sync) ==========
// C[4096,1024] = Xh @ Wt^T + bias. A,B both bf16 K-major. 128x128 CTA tile,
// 8 warps (2m x 4n), BK=32, smem double buffered, straight uint4 staging.
// grid = (8, 32, 2)  z: 0->Q, 1->K
__global__ void __launch_bounds__(256)
qkproj_bf16(const float* __restrict__ bq, const float* __restrict__ bk)
{
    const int z = blockIdx.z;
    const __nv_bfloat16* Wz = g_Wt + (size_t)z * H * H;
    const float* bias = z ? bk : bq;
    __nv_bfloat16* C  = z ? g_Kh : g_Qh;
    const int n0 = blockIdx.x * 128;
    const int m0 = blockIdx.y * 128;

    // word = bf16x2 k-pair; [row][kpair] pitch 20 -> conflict-free frag LDS
    __shared__ __align__(16) uint32_t Xs[2][128][20];
    __shared__ __align__(16) uint32_t Ws[2][128][20];

    const int tid  = threadIdx.x;
    const int lane = tid & 31;
    const int wid  = tid >> 5;
    const int wm   = wid >> 2;          // 0..1
    const int wn   = wid & 3;           // 0..3
    const int fr   = lane >> 2;         // 0..7
    const int fc   = lane & 3;          // 0..3

    // staging: row = tid>>1 (0..127), 16 bf16 (8 words) at word offset kp0
    const int row = tid >> 1;
    const int kp0 = (tid & 1) * 8;
    const __nv_bfloat16* arow = g_Xh + (size_t)(m0 + row) * H + kp0 * 2;
    const __nv_bfloat16* brow = Wz   + (size_t)(n0 + row) * H + kp0 * 2;

    float acc[4][4][4];
#pragma unroll
    for (int i = 0; i < 4; i++)
#pragma unroll
        for (int j = 0; j < 4; j++)
#pragma unroll
            for (int q = 0; q < 4; q++) acc[i][j][q] = 0.f;

    uint4 a0, a1, b0, b1;
    a0 = *(const uint4*)&arow[0];
    a1 = *(const uint4*)&arow[8];
    b0 = *(const uint4*)&brow[0];
    b1 = *(const uint4*)&brow[8];
    *(uint4*)&Xs[0][row][kp0]     = a0;
    *(uint4*)&Xs[0][row][kp0 + 4] = a1;
    *(uint4*)&Ws[0][row][kp0]     = b0;
    *(uint4*)&Ws[0][row][kp0 + 4] = b1;
    __syncthreads();

    const int NIT = H / 32;   // 32
    for (int it = 0; it < NIT; it++) {
        const int buf = it & 1;
        if (it < NIT - 1) {
            const int ko = (it + 1) * 32;   // bf16 offset
            a0 = *(const uint4*)&arow[ko];
            a1 = *(const uint4*)&arow[ko + 8];
            b0 = *(const uint4*)&brow[ko];
            b1 = *(const uint4*)&brow[ko + 8];
        }
#pragma unroll
        for (int ks = 0; ks < 2; ks++) {     // two k16 chunks
            uint32_t af[4][4], bf[4][2];
#pragma unroll
            for (int tm = 0; tm < 4; tm++) {
                const int mb = wm * 64 + tm * 16;
                af[tm][0] = Xs[buf][mb + fr][ks * 8 + fc];
                af[tm][1] = Xs[buf][mb + fr + 8][ks * 8 + fc];
                af[tm][2] = Xs[buf][mb + fr][ks * 8 + fc + 4];
                af[tm][3] = Xs[buf][mb + fr + 8][ks * 8 + fc + 4];
            }
#pragma unroll
            for (int tn = 0; tn < 4; tn++) {
                const int nb = wn * 32 + tn * 8 + fr;
                bf[tn][0] = Ws[buf][nb][ks * 8 + fc];
                bf[tn][1] = Ws[buf][nb][ks * 8 + fc + 4];
            }
#pragma unroll
            for (int tm = 0; tm < 4; tm++)
#pragma unroll
                for (int tn = 0; tn < 4; tn++)
                    mma_bf16(acc[tm][tn], af[tm], bf[tn]);
        }
        if (it < NIT - 1) {
            const int nb2 = buf ^ 1;
            *(uint4*)&Xs[nb2][row][kp0]     = a0;
            *(uint4*)&Xs[nb2][row][kp0 + 4] = a1;
            *(uint4*)&Ws[nb2][row][kp0]     = b0;
            *(uint4*)&Ws[nb2][row][kp0 + 4] = b1;
        }
        __syncthreads();
    }

#pragma unroll
    for (int tm = 0; tm < 4; tm++)
#pragma unroll
        for (int tn = 0; tn < 4; tn++) {
            const int r   = m0 + wm * 64 + tm * 16 + fr;
            const int col = n0 + wn * 32 + tn * 8 + 2 * fc;
            const float c0 = bias[col], c1 = bias[col + 1];
            __nv_bfloat162 o;
            o = __floats2bfloat162_rn(acc[tm][tn][0] + c0, acc[tm][tn][1] + c1);
            *(__nv_bfloat162*)&C[(size_t)r * H + col] = o;
            o = __floats2bfloat162_rn(acc[tm][tn][2] + c0, acc[tm][tn][3] + c1);
            *(__nv_bfloat162*)&C[(size_t)(r + 8) * H + col] = o;
        }
}

// ======================= Kernel 2: V projection, split-K fp32 ==============
// Partial c handles k in [c*256, c*256+256). grid = (B*T/64, 4).
__global__ void vproj_kernel(const float* __restrict__ x,
                             const float* __restrict__ Wv)
{
    const int m0 = blockIdx.x * 64;
    const int kbase = blockIdx.y * (H / 4);
    float* Cp = g_Vp + (size_t)blockIdx.y * B * T * D;

    __shared__ float As[64][17];
    __shared__ float Bs[16][65];

    const int tx = threadIdx.x, ty = threadIdx.y;
    const int tid = ty * 16 + tx;

    float acc[4][4];
#pragma unroll
    for (int i = 0; i < 4; i++)
#pragma unroll
        for (int j = 0; j < 4; j++) acc[i][j] = 0.f;

    for (int kc = 0; kc < H / 4; kc += 16) {
        const int k0 = kbase + kc;
#pragma unroll
        for (int i = 0; i < 4; i++) {
            int idx = tid + i * 256;
            int r = idx >> 4, c = idx & 15;
            As[r][c] = x[(size_t)(m0 + r) * H + k0 + c];
        }
#pragma unroll
        for (int i = 0; i < 4; i++) {
            int idx = tid + i * 256;
            int r = idx >> 6, c = idx & 63;
            Bs[r][c] = Wv[(size_t)(k0 + r) * D + c];
        }
        __syncthreads();
#pragma unroll
        for (int kk = 0; kk < 16; kk++) {
            float a[4], bb[4];
#pragma unroll
            for (int i = 0; i < 4; i++) a[i]  = As[ty * 4 + i][kk];
#pragma unroll
            for (int j = 0; j < 4; j++) bb[j] = Bs[kk][tx * 4 + j];
#pragma unroll
            for (int i = 0; i < 4; i++)
#pragma unroll
                for (int j = 0; j < 4; j++) acc[i][j] += a[i] * bb[j];
        }
        __syncthreads();
    }
#pragma unroll
    for (int i = 0; i < 4; i++)
#pragma unroll
        for (int j = 0; j < 4; j++)
            Cp[(size_t)(m0 + ty * 4 + i) * D + tx * 4 + j] = acc[i][j];
}

// vsum: g_V = sum of 4 partials + bias. grid = B*T*D/256, block 256.
__global__ void vsum_kernel(const float* __restrict__ bv)
{
    const size_t i = (size_t)blockIdx.x * 256 + threadIdx.x;
    const size_t N = (size_t)B * T * D;
    g_V[i] = g_Vp[i] + g_Vp[N + i] + g_Vp[2 * N + i] + g_Vp[3 * N + i]
           + bv[i & 63];
}

// ======================= Kernel 3: scores (bf16 mma.sync) ==================
__global__ void __launch_bounds__(256)
scores_bf16()
{
    const int st = blockIdx.x;
    const int tt = blockIdx.y;
    if (st > tt) return;
    const int z = blockIdx.z;
    const int n = z >> 1, b = z & 1;

    const __nv_bfloat16* Qb = g_Qh + (size_t)b * T * H + (size_t)n * D;
    const __nv_bfloat16* Kb = g_Kh + (size_t)b * T * H + (size_t)n * D;
    __half* Wp = g_Wh + (size_t)z * T * T;

    const int t0 = tt * 128, s0 = st * 128;

    __shared__ __align__(16) uint32_t Qs2[128][36];
    __shared__ __align__(16) uint32_t Ks2[128][36];
    __shared__ float rs[128][4];

    const int tid  = threadIdx.x;
    const int lane = tid & 31;
    const int wid  = tid >> 5;
    const int wm   = wid >> 2;
    const int wn   = wid & 3;
    const int fr   = lane >> 2;
    const int fc   = lane & 3;

    const int sr = tid >> 1;
    const int sc = (tid & 1) * 32;
#pragma unroll
    for (int u = 0; u < 4; u++) {
        uint4 q4 = *(const uint4*)&Qb[(size_t)(t0 + sr) * H + sc + u * 8];
        uint4 k4 = *(const uint4*)&Kb[(size_t)(s0 + sr) * H + sc + u * 8];
        *(uint4*)&Qs2[sr][sc / 2 + u * 4] = q4;
        *(uint4*)&Ks2[sr][sc / 2 + u * 4] = k4;
    }
    __syncthreads();

    float acc[4][4][4];
#pragma unroll
    for (int i = 0; i < 4; i++)
#pragma unroll
        for (int j = 0; j < 4; j++)
#pragma unroll
            for (int q = 0; q < 4; q++) acc[i][j][q] = 0.f;

#pragma unroll
    for (int ks = 0; ks < 4; ks++) {
        uint32_t af[4][4], bf[4][2];
#pragma unroll
        for (int tm = 0; tm < 4; tm++) {
            const int mb = wm * 64 + tm * 16;
            af[tm][0] = Qs2[mb + fr][ks * 8 + fc];
            af[tm][1] = Qs2[mb + fr + 8][ks * 8 + fc];
            af[tm][2] = Qs2[mb + fr][ks * 8 + fc + 4];
            af[tm][3] = Qs2[mb + fr + 8][ks * 8 + fc + 4];
        }
#pragma unroll
        for (int tn = 0; tn < 4; tn++) {
            const int nb = wn * 32 + tn * 8 + fr;
            bf[tn][0] = Ks2[nb][ks * 8 + fc];
            bf[tn][1] = Ks2[nb][ks * 8 + fc + 4];
        }
#pragma unroll
        for (int tm = 0; tm < 4; tm++)
#pragma unroll
            for (int tn = 0; tn < 4; tn++)
                mma_bf16(acc[tm][tn], af[tm], bf[tn]);
    }

    const bool diag = (st == tt);
#pragma unroll
    for (int tm = 0; tm < 4; tm++)
#pragma unroll
        for (int rq = 0; rq < 2; rq++) {
            const int rloc = wm * 64 + tm * 16 + fr + rq * 8;
            const int t = t0 + rloc;
            float rsum = 0.f;
#pragma unroll
            for (int tn = 0; tn < 4; tn++) {
                const int s = s0 + wn * 32 + tn * 8 + 2 * fc;
                float e0 = __expf(acc[tm][tn][rq * 2 + 0] * SCALE);
                float e1 = __expf(acc[tm][tn][rq * 2 + 1] * SCALE);
                if (diag) {
                    if (s     > t) e0 = 0.f;
                    if (s + 1 > t) e1 = 0.f;
                }
                rsum += e0 + e1;
                *(__half2*)&Wp[(size_t)t * T + s] = __floats2half2_rn(e0, e1);
            }
            rsum += __shfl_xor_sync(0xffffffffu, rsum, 1);
            rsum += __shfl_xor_sync(0xffffffffu, rsum, 2);
            if (fc == 0) rs[rloc][wn] = rsum;
        }
    __syncthreads();
    if (tid < 128) {
        float v = rs[tid][0] + rs[tid][1] + rs[tid][2] + rs[tid][3];
        g_RS[((size_t)z * T + t0 + tid) * 16 + st] = v;
    }
}

// ======================= Kernel 4: streaming mean-of-softmax ===============
__global__ void __launch_bounds__(256)
softmax_mean_kernel(float* __restrict__ out_mean)
{
    const int row = blockIdx.x;   // b*T + t
    const int b = row >> 11;
    const int t = row & 2047;
    const int tid = threadIdx.x;

    const int nst = (t >> 7) + 1;
    const int L   = nst * 128;

    __shared__ float sinv[NH];
    if (tid < NH) {
        const float* p = g_RS + ((size_t)(tid * B + b) * T + t) * 16;
        float s = 0.f;
        for (int i = 0; i < nst; i++) s += p[i];
        sinv[tid] = (1.0f / NH) / s;
    }
    __syncthreads();

    const int c0 = tid * 8;
    float acc[8];
#pragma unroll
    for (int i = 0; i < 8; i++) acc[i] = 0.f;

    if (c0 < L) {
        const size_t rowoff = ((size_t)b * T + t) * T + c0;
#pragma unroll
        for (int n = 0; n < NH; n++) {
            const __half* p = g_Wh + (size_t)n * (B * (size_t)T * T) + rowoff;
            uint4 u = *(const uint4*)p;
            const float w = sinv[n];
            float2 f;
            f = __half22float2(*(__half2*)&u.x); acc[0] += f.x * w; acc[1] += f.y * w;
            f = __half22float2(*((__half2*)&u.x + 1)); acc[2] += f.x * w; acc[3] += f.y * w;
            f = __half22float2(*(__half2*)&u.z); acc[4] += f.x * w; acc[5] += f.y * w;
            f = __half22float2(*((__half2*)&u.z + 1)); acc[6] += f.x * w; acc[7] += f.y * w;
        }
    }

    float* mrow = out_mean + (size_t)row * T + c0;
    *(float4*)&mrow[0] = make_float4(acc[0], acc[1], acc[2], acc[3]);
    *(float4*)&mrow[4] = make_float4(acc[4], acc[5], acc[6], acc[7]);
}

// ======================= Kernel 5: AV (head-mean identity, 8 chunks) =======
__global__ void av_kernel(const float* __restrict__ mean_w)
{
    const int t_tile = blockIdx.x;
    const int b      = blockIdx.y;
    const int chunk  = blockIdx.z;
    const int t0 = t_tile * 64;

    __shared__ float Ws[64][65];
    __shared__ float Vs[64][65];

    const int tx = threadIdx.x, ty = threadIdx.y;
    const int tid = ty * 16 + tx;

    float acc[4][4];
#pragma unroll
    for (int i = 0; i < 4; i++)
#pragma unroll
        for (int j = 0; j < 4; j++) acc[i][j] = 0.f;

    const int st_begin = chunk * 4;
    const int st_end   = min(chunk * 4 + 4, t_tile + 1);

    for (int st = st_begin; st < st_end; st++) {
        const int s0 = st * 64;
#pragma unroll
        for (int i = 0; i < 16; i++) {
            int idx = tid + i * 256;
            int r = idx >> 6, c = idx & 63;
            Ws[r][c] = mean_w[((size_t)b * T + t0 + r) * T + s0 + c];
            Vs[r][c] = g_V[((size_t)b * T + s0 + r) * D + c];
        }
        __syncthreads();
#pragma unroll 8
        for (int kk = 0; kk < 64; kk++) {
            float a[4], bb[4];
#pragma unroll
            for (int i = 0; i < 4; i++) a[i]  = Ws[ty * 4 + i][kk];
#pragma unroll
            for (int j = 0; j < 4; j++) bb[j] = Vs[kk][tx * 4 + j];
#pragma unroll
            for (int i = 0; i < 4; i++)
#pragma unroll
                for (int j = 0; j < 4; j++) acc[i][j] += a[i] * bb[j];
        }
        __syncthreads();
    }

    float* Cp = g_MHp + (size_t)chunk * B * T * D;
#pragma unroll
    for (int i = 0; i < 4; i++)
#pragma unroll
        for (int j = 0; j < 4; j++)
            Cp[((size_t)b * T + t0 + ty * 4 + i) * D + tx * 4 + j] = acc[i][j];
}

// ======================= Kernel 6: output projection =======================
__global__ void out_kernel(const float* __restrict__ Wo,
                           const float* __restrict__ bo,
                           float* __restrict__ out)
{
    const int n0 = blockIdx.x * 64;
    const int m0 = blockIdx.y * 64;

    __shared__ float As[64][65];
    __shared__ float Bs[64][65];

    const int tx = threadIdx.x, ty = threadIdx.y;
    const int tid = ty * 16 + tx;

    const size_t N = (size_t)B * T * D;
#pragma unroll
    for (int i = 0; i < 16; i++) {
        int idx = tid + i * 256;
        int r = idx >> 6, c = idx & 63;
        size_t mi = (size_t)(m0 + r) * D + c;
        float v = 0.f;
#pragma unroll
        for (int p = 0; p < 8; p++) v += g_MHp[p * N + mi];
        As[r][c] = v;
        Bs[r][c] = Wo[(size_t)r * H + n0 + c];
    }
    __syncthreads();

    float acc[4][4];
#pragma unroll
    for (int i = 0; i < 4; i++)
#pragma unroll
        for (int j = 0; j < 4; j++) acc[i][j] = 0.f;

#pragma unroll 8
    for (int kk = 0; kk < 64; kk++) {
        float a[4], bb[4];
#pragma unroll
        for (int i = 0; i < 4; i++) a[i]  = As[ty * 4 + i][kk];
#pragma unroll
        for (int j = 0; j < 4; j++) bb[j] = Bs[kk][tx * 4 + j];
#pragma unroll
        for (int i = 0; i < 4; i++)
#pragma unroll
            for (int j = 0; j < 4; j++) acc[i][j] += a[i] * bb[j];
    }

#pragma unroll
    for (int i = 0; i < 4; i++)
#pragma unroll
        for (int j = 0; j < 4; j++)
            out[(size_t)(m0 + ty * 4 + i) * H + n0 + tx * 4 + j] =
                acc[i][j] + bo[n0 + tx * 4 + j];
}

// ---------------------------------------------------------------------------
extern "C" void kernel_launch(void* const* d_in, const int* in_sizes, int n_in,
                              void* d_out, int out_size)
{
    const float* x  = (const float*)d_in[0];
    const float* Wq = (const float*)d_in[1];
    const float* bq = (const float*)d_in[2];
    const float* Wk = (const float*)d_in[3];
    const float* bk = (const float*)d_in[4];
    const float* Wv = (const float*)d_in[5];
    const float* bv = (const float*)d_in[6];
    const float* Wo = (const float*)d_in[7];
    const float* bo = (const float*)d_in[8];

    float* out      = (float*)d_out;                 // [B,T,H]
    float* mean_out = out + (size_t)B * T * H;       // [B,T,T]

    dim3 blk16(16, 16);

    xcast_kernel       <<<B * T, 256>>>(x);
    wtrans_kernel      <<<dim3(32, 32, 2), dim3(32, 8)>>>(Wq, Wk);
    vproj_kernel       <<<dim3((B * T) / 64, 4), blk16>>>(x, Wv);
    vsum_kernel        <<<(B * T * D) / 256, 256>>>(bv);
    qkproj_bf16        <<<dim3(H / 128, (B * T) / 128, 2), 256>>>(bq, bk);
    scores_bf16        <<<dim3(T / 128, T / 128, NH * B), 256>>>();
    softmax_mean_kernel<<<B * T, 256>>>(mean_out);
    av_kernel          <<<dim3(T / 64, B, 8), blk16>>>(mean_out);
    out_kernel         <<<dim3(H / 64, (B * T) / 64), blk16>>>(Wo, bo, out);
}

// round 9
// speedup vs baseline: 1.4463x; 1.4463x over previous
#include <cuda_runtime.h>
#include <cuda_fp16.h>
#include <cuda_bf16.h>
#include <math.h>
#include <stdint.h>

#define B    2
#define T    2048
#define H    1024
#define NH   16
#define D    64
#define SCALE 0.125f   // D^-0.5

// ---------------- static device scratch (no dynamic allocation allowed) ----
// Q,K layout: [B*T, NH*D] row-major bf16 (row = b*T+t, col = n*64+d)
__device__ __nv_bfloat16 g_Qh[(size_t)B * T * H];   // 8 MB
__device__ __nv_bfloat16 g_Kh[(size_t)B * T * H];   // 8 MB
__device__ float  g_Vp[(size_t)4 * B * T * D];      // 4 MB V split-K partials
__device__ float  g_V[(size_t)B * T * D];           // 1 MB
__device__ __half g_Wh[(size_t)NH * B * T * T];     // 268 MB exp(score) fp16
__device__ float  g_RS[(size_t)NH * B * T * 16];    // 4 MB per-(row,s-tile) exp sums
__device__ float  g_MHp[(size_t)8 * B * T * D];     // 8 MB AV partials (8 chunks)

// ---------------------------------------------------------------------------
__device__ __forceinline__ uint32_t pack_bf2(float lo, float hi) {
    __nv_bfloat162 h = __floats2bfloat162_rn(lo, hi);
    return *(uint32_t*)&h;
}

__device__ __forceinline__ void mma_bf16(float* d, const uint32_t* a, const uint32_t* b) {
    asm volatile(
        "mma.sync.aligned.m16n8k16.row.col.f32.bf16.bf16.f32 "
        "{%0,%1,%2,%3}, {%4,%5,%6,%7}, {%8,%9}, {%0,%1,%2,%3};"
        : "+f"(d[0]), "+f"(d[1]), "+f"(d[2]), "+f"(d[3])
        : "r"(a[0]), "r"(a[1]), "r"(a[2]), "r"(a[3]), "r"(b[0]), "r"(b[1]));
}

// ---------------------------------------------------------------------------
// Kernel 1: batched Q/K projection, bf16 tensor cores, fp32 accumulate.
// (EXACT R6 version — known good at ~140us.)
// C[4096,1024] = x @ Wbig + bias, Wbig(h,col)=W[(col>>6)*H*D + h*64 + (col&63)].
// 128x128 CTA tile, 8 warps (2m x 4n), warp tile 64x32, BK=32, double buffered.
// Output stored as bf16. grid = (8, 32, 2)  z: 0->Q, 1->K
// ---------------------------------------------------------------------------
__global__ void __launch_bounds__(256)
qkproj_bf16(const float* __restrict__ x,
            const float* __restrict__ Wq, const float* __restrict__ bq,
            const float* __restrict__ Wk, const float* __restrict__ bk)
{
    const float* Wm    = blockIdx.z ? Wk : Wq;
    const float* bias  = blockIdx.z ? bk : bq;
    __nv_bfloat16* C   = blockIdx.z ? g_Kh : g_Qh;
    const int n0 = blockIdx.x * 128;
    const int m0 = blockIdx.y * 128;

    // word = bf16x2 (k-pair). As2: [m][kpair] pitch 20; Bs2: [kpair][n] pitch 136.
    __shared__ __align__(16) uint32_t As2[2][128][20];
    __shared__ __align__(16) uint32_t Bs2[2][16][136];

    const int tid  = threadIdx.x;
    const int lane = tid & 31;
    const int wid  = tid >> 5;
    const int wm   = wid >> 2;          // 0..1
    const int wn   = wid & 3;           // 0..3
    const int fr   = lane >> 2;         // 0..7
    const int fc   = lane & 3;          // 0..3

    // A staging: row am, 16 k-values starting at ak
    const int am = tid >> 1;
    const int ak = (tid & 1) * 16;
    const float* xrow = x + (size_t)(m0 + am) * H + ak;
    // B staging: k-pair p (rows 2p,2p+1), 8 cols starting at nn
    const int p  = tid >> 4;            // 0..15
    const int nn = (tid & 15) * 8;      // 0..120
    const int bcol = n0 + nn;
    const size_t bbase = (size_t)(bcol >> 6) * (H * D) + (size_t)(bcol & 63);

    float acc[4][4][4];
#pragma unroll
    for (int i = 0; i < 4; i++)
#pragma unroll
        for (int j = 0; j < 4; j++)
#pragma unroll
            for (int q = 0; q < 4; q++) acc[i][j][q] = 0.f;

    float4 a0, a1, a2, a3, blo0, blo1, bhi0, bhi1;

    // prologue: load iter 0 (k0 = 0)
    a0 = *(const float4*)&xrow[0];
    a1 = *(const float4*)&xrow[4];
    a2 = *(const float4*)&xrow[8];
    a3 = *(const float4*)&xrow[12];
    blo0 = *(const float4*)&Wm[bbase + (size_t)(2 * p)     * D];
    blo1 = *(const float4*)&Wm[bbase + (size_t)(2 * p)     * D + 4];
    bhi0 = *(const float4*)&Wm[bbase + (size_t)(2 * p + 1) * D];
    bhi1 = *(const float4*)&Wm[bbase + (size_t)(2 * p + 1) * D + 4];
    {
        uint4 u;
        u.x = pack_bf2(a0.x, a0.y); u.y = pack_bf2(a0.z, a0.w);
        u.z = pack_bf2(a1.x, a1.y); u.w = pack_bf2(a1.z, a1.w);
        *(uint4*)&As2[0][am][ak / 2] = u;
        u.x = pack_bf2(a2.x, a2.y); u.y = pack_bf2(a2.z, a2.w);
        u.z = pack_bf2(a3.x, a3.y); u.w = pack_bf2(a3.z, a3.w);
        *(uint4*)&As2[0][am][ak / 2 + 4] = u;
        u.x = pack_bf2(blo0.x, bhi0.x); u.y = pack_bf2(blo0.y, bhi0.y);
        u.z = pack_bf2(blo0.z, bhi0.z); u.w = pack_bf2(blo0.w, bhi0.w);
        *(uint4*)&Bs2[0][p][nn] = u;
        u.x = pack_bf2(blo1.x, bhi1.x); u.y = pack_bf2(blo1.y, bhi1.y);
        u.z = pack_bf2(blo1.z, bhi1.z); u.w = pack_bf2(blo1.w, bhi1.w);
        *(uint4*)&Bs2[0][p][nn + 4] = u;
    }
    __syncthreads();

    const int NIT = H / 32;   // 32
    for (int it = 0; it < NIT; it++) {
        const int buf = it & 1;
        if (it < NIT - 1) {
            const int k0 = (it + 1) * 32;
            a0 = *(const float4*)&xrow[k0];
            a1 = *(const float4*)&xrow[k0 + 4];
            a2 = *(const float4*)&xrow[k0 + 8];
            a3 = *(const float4*)&xrow[k0 + 12];
            blo0 = *(const float4*)&Wm[bbase + (size_t)(k0 + 2 * p)     * D];
            blo1 = *(const float4*)&Wm[bbase + (size_t)(k0 + 2 * p)     * D + 4];
            bhi0 = *(const float4*)&Wm[bbase + (size_t)(k0 + 2 * p + 1) * D];
            bhi1 = *(const float4*)&Wm[bbase + (size_t)(k0 + 2 * p + 1) * D + 4];
        }
#pragma unroll
        for (int ks = 0; ks < 2; ks++) {     // two k16 chunks per stage
            uint32_t af[4][4], bf[4][2];
#pragma unroll
            for (int tm = 0; tm < 4; tm++) {
                const int mb = wm * 64 + tm * 16;
                af[tm][0] = As2[buf][mb + fr][ks * 8 + fc];
                af[tm][1] = As2[buf][mb + fr + 8][ks * 8 + fc];
                af[tm][2] = As2[buf][mb + fr][ks * 8 + fc + 4];
                af[tm][3] = As2[buf][mb + fr + 8][ks * 8 + fc + 4];
            }
#pragma unroll
            for (int tn = 0; tn < 4; tn++) {
                const int nb = wn * 32 + tn * 8 + fr;
                bf[tn][0] = Bs2[buf][ks * 8 + fc][nb];
                bf[tn][1] = Bs2[buf][ks * 8 + fc + 4][nb];
            }
#pragma unroll
            for (int tm = 0; tm < 4; tm++)
#pragma unroll
                for (int tn = 0; tn < 4; tn++)
                    mma_bf16(acc[tm][tn], af[tm], bf[tn]);
        }
        if (it < NIT - 1) {
            const int nb2 = (it & 1) ^ 1;
            uint4 u;
            u.x = pack_bf2(a0.x, a0.y); u.y = pack_bf2(a0.z, a0.w);
            u.z = pack_bf2(a1.x, a1.y); u.w = pack_bf2(a1.z, a1.w);
            *(uint4*)&As2[nb2][am][ak / 2] = u;
            u.x = pack_bf2(a2.x, a2.y); u.y = pack_bf2(a2.z, a2.w);
            u.z = pack_bf2(a3.x, a3.y); u.w = pack_bf2(a3.z, a3.w);
            *(uint4*)&As2[nb2][am][ak / 2 + 4] = u;
            u.x = pack_bf2(blo0.x, bhi0.x); u.y = pack_bf2(blo0.y, bhi0.y);
            u.z = pack_bf2(blo0.z, bhi0.z); u.w = pack_bf2(blo0.w, bhi0.w);
            *(uint4*)&Bs2[nb2][p][nn] = u;
            u.x = pack_bf2(blo1.x, bhi1.x); u.y = pack_bf2(blo1.y, bhi1.y);
            u.z = pack_bf2(blo1.z, bhi1.z); u.w = pack_bf2(blo1.w, bhi1.w);
            *(uint4*)&Bs2[nb2][p][nn + 4] = u;
        }
        __syncthreads();
    }

#pragma unroll
    for (int tm = 0; tm < 4; tm++)
#pragma unroll
        for (int tn = 0; tn < 4; tn++) {
            const int row = m0 + wm * 64 + tm * 16 + fr;
            const int col = n0 + wn * 32 + tn * 8 + 2 * fc;
            const float b0 = bias[col], b1 = bias[col + 1];
            __nv_bfloat162 o;
            o = __floats2bfloat162_rn(acc[tm][tn][0] + b0, acc[tm][tn][1] + b1);
            *(__nv_bfloat162*)&C[(size_t)row * H + col] = o;
            o = __floats2bfloat162_rn(acc[tm][tn][2] + b0, acc[tm][tn][3] + b1);
            *(__nv_bfloat162*)&C[(size_t)(row + 8) * H + col] = o;
        }
}

// ---------------------------------------------------------------------------
// Kernel 2: V projection, split-K fp32. Partial c: k in [c*256, c*256+256).
// grid = (B*T/64, 4).
// ---------------------------------------------------------------------------
__global__ void vproj_kernel(const float* __restrict__ x,
                             const float* __restrict__ Wv)
{
    const int m0 = blockIdx.x * 64;
    const int kbase = blockIdx.y * (H / 4);
    float* Cp = g_Vp + (size_t)blockIdx.y * B * T * D;

    __shared__ float As[64][17];
    __shared__ float Bs[16][65];

    const int tx = threadIdx.x, ty = threadIdx.y;
    const int tid = ty * 16 + tx;

    float acc[4][4];
#pragma unroll
    for (int i = 0; i < 4; i++)
#pragma unroll
        for (int j = 0; j < 4; j++) acc[i][j] = 0.f;

    for (int kc = 0; kc < H / 4; kc += 16) {
        const int k0 = kbase + kc;
#pragma unroll
        for (int i = 0; i < 4; i++) {
            int idx = tid + i * 256;
            int r = idx >> 4, c = idx & 15;
            As[r][c] = x[(size_t)(m0 + r) * H + k0 + c];
        }
#pragma unroll
        for (int i = 0; i < 4; i++) {
            int idx = tid + i * 256;
            int r = idx >> 6, c = idx & 63;
            Bs[r][c] = Wv[(size_t)(k0 + r) * D + c];
        }
        __syncthreads();
#pragma unroll
        for (int kk = 0; kk < 16; kk++) {
            float a[4], bb[4];
#pragma unroll
            for (int i = 0; i < 4; i++) a[i]  = As[ty * 4 + i][kk];
#pragma unroll
            for (int j = 0; j < 4; j++) bb[j] = Bs[kk][tx * 4 + j];
#pragma unroll
            for (int i = 0; i < 4; i++)
#pragma unroll
                for (int j = 0; j < 4; j++) acc[i][j] += a[i] * bb[j];
        }
        __syncthreads();
    }
#pragma unroll
    for (int i = 0; i < 4; i++)
#pragma unroll
        for (int j = 0; j < 4; j++)
            Cp[(size_t)(m0 + ty * 4 + i) * D + tx * 4 + j] = acc[i][j];
}

// vsum: g_V = sum of 4 partials + bias. grid = B*T*D/256, block 256.
__global__ void vsum_kernel(const float* __restrict__ bv)
{
    const size_t i = (size_t)blockIdx.x * 256 + threadIdx.x;
    const size_t N = (size_t)B * T * D;
    g_V[i] = g_Vp[i] + g_Vp[N + i] + g_Vp[2 * N + i] + g_Vp[3 * N + i]
           + bv[i & 63];
}

// ---------------------------------------------------------------------------
// Kernel 3: scores via bf16 mma (causal 128-tiles only). Epilogue: exp,
// exact-zero above diagonal, fp16 store, deterministic per-(row,s-tile) sums.
// grid = (16,16,NH*B), z = n*2+b.  (EXACT R6 version.)
// ---------------------------------------------------------------------------
__global__ void __launch_bounds__(256)
scores_bf16()
{
    const int st = blockIdx.x;
    const int tt = blockIdx.y;
    if (st > tt) return;
    const int z = blockIdx.z;
    const int n = z >> 1, b = z & 1;

    const __nv_bfloat16* Qb = g_Qh + (size_t)b * T * H + (size_t)n * D;
    const __nv_bfloat16* Kb = g_Kh + (size_t)b * T * H + (size_t)n * D;
    __half* Wp = g_Wh + (size_t)z * T * T;

    const int t0 = tt * 128, s0 = st * 128;

    __shared__ __align__(16) uint32_t Qs2[128][36];
    __shared__ __align__(16) uint32_t Ks2[128][36];
    __shared__ float rs[128][4];

    const int tid  = threadIdx.x;
    const int lane = tid & 31;
    const int wid  = tid >> 5;
    const int wm   = wid >> 2;
    const int wn   = wid & 3;
    const int fr   = lane >> 2;
    const int fc   = lane & 3;

    const int sr = tid >> 1;
    const int sc = (tid & 1) * 32;
#pragma unroll
    for (int u = 0; u < 4; u++) {
        uint4 q4 = *(const uint4*)&Qb[(size_t)(t0 + sr) * H + sc + u * 8];
        uint4 k4 = *(const uint4*)&Kb[(size_t)(s0 + sr) * H + sc + u * 8];
        *(uint4*)&Qs2[sr][sc / 2 + u * 4] = q4;
        *(uint4*)&Ks2[sr][sc / 2 + u * 4] = k4;
    }
    __syncthreads();

    float acc[4][4][4];
#pragma unroll
    for (int i = 0; i < 4; i++)
#pragma unroll
        for (int j = 0; j < 4; j++)
#pragma unroll
            for (int q = 0; q < 4; q++) acc[i][j][q] = 0.f;

#pragma unroll
    for (int ks = 0; ks < 4; ks++) {
        uint32_t af[4][4], bf[4][2];
#pragma unroll
        for (int tm = 0; tm < 4; tm++) {
            const int mb = wm * 64 + tm * 16;
            af[tm][0] = Qs2[mb + fr][ks * 8 + fc];
            af[tm][1] = Qs2[mb + fr + 8][ks * 8 + fc];
            af[tm][2] = Qs2[mb + fr][ks * 8 + fc + 4];
            af[tm][3] = Qs2[mb + fr + 8][ks * 8 + fc + 4];
        }
#pragma unroll
        for (int tn = 0; tn < 4; tn++) {
            const int nb = wn * 32 + tn * 8 + fr;
            bf[tn][0] = Ks2[nb][ks * 8 + fc];
            bf[tn][1] = Ks2[nb][ks * 8 + fc + 4];
        }
#pragma unroll
        for (int tm = 0; tm < 4; tm++)
#pragma unroll
            for (int tn = 0; tn < 4; tn++)
                mma_bf16(acc[tm][tn], af[tm], bf[tn]);
    }

    const bool diag = (st == tt);
#pragma unroll
    for (int tm = 0; tm < 4; tm++)
#pragma unroll
        for (int rq = 0; rq < 2; rq++) {
            const int rloc = wm * 64 + tm * 16 + fr + rq * 8;
            const int t = t0 + rloc;
            float rsum = 0.f;
#pragma unroll
            for (int tn = 0; tn < 4; tn++) {
                const int s = s0 + wn * 32 + tn * 8 + 2 * fc;
                float e0 = __expf(acc[tm][tn][rq * 2 + 0] * SCALE);
                float e1 = __expf(acc[tm][tn][rq * 2 + 1] * SCALE);
                if (diag) {
                    if (s     > t) e0 = 0.f;
                    if (s + 1 > t) e1 = 0.f;
                }
                rsum += e0 + e1;
                *(__half2*)&Wp[(size_t)t * T + s] = __floats2half2_rn(e0, e1);
            }
            rsum += __shfl_xor_sync(0xffffffffu, rsum, 1);
            rsum += __shfl_xor_sync(0xffffffffu, rsum, 2);
            if (fc == 0) rs[rloc][wn] = rsum;
        }
    __syncthreads();
    if (tid < 128) {
        float v = rs[tid][0] + rs[tid][1] + rs[tid][2] + rs[tid][3];
        g_RS[((size_t)z * T + t0 + tid) * 16 + st] = v;
    }
}

// ---------------------------------------------------------------------------
// Kernel 4: streaming mean-of-softmax. One block per (b,t), 256 threads.
// (EXACT R6 version.)
// ---------------------------------------------------------------------------
__global__ void __launch_bounds__(256)
softmax_mean_kernel(float* __restrict__ out_mean)
{
    const int row = blockIdx.x;   // b*T + t
    const int b = row >> 11;
    const int t = row & 2047;
    const int tid = threadIdx.x;

    const int nst = (t >> 7) + 1;
    const int L   = nst * 128;

    __shared__ float sinv[NH];
    if (tid < NH) {
        const float* p = g_RS + ((size_t)(tid * B + b) * T + t) * 16;
        float s = 0.f;
        for (int i = 0; i < nst; i++) s += p[i];
        sinv[tid] = (1.0f / NH) / s;
    }
    __syncthreads();

    const int c0 = tid * 8;
    float acc[8];
#pragma unroll
    for (int i = 0; i < 8; i++) acc[i] = 0.f;

    if (c0 < L) {
        const size_t rowoff = ((size_t)b * T + t) * T + c0;
#pragma unroll
        for (int n = 0; n < NH; n++) {
            const __half* p = g_Wh + (size_t)n * (B * (size_t)T * T) + rowoff;
            uint4 u = *(const uint4*)p;
            const float w = sinv[n];
            float2 f;
            f = __half22float2(*(__half2*)&u.x); acc[0] += f.x * w; acc[1] += f.y * w;
            f = __half22float2(*((__half2*)&u.x + 1)); acc[2] += f.x * w; acc[3] += f.y * w;
            f = __half22float2(*(__half2*)&u.z); acc[4] += f.x * w; acc[5] += f.y * w;
            f = __half22float2(*((__half2*)&u.z + 1)); acc[6] += f.x * w; acc[7] += f.y * w;
        }
    }

    float* mrow = out_mean + (size_t)row * T + c0;
    *(float4*)&mrow[0] = make_float4(acc[0], acc[1], acc[2], acc[3]);
    *(float4*)&mrow[4] = make_float4(acc[4], acc[5], acc[6], acc[7]);
}

// ---------------------------------------------------------------------------
// Kernel 5: AV via head-mean identity, 8 s-chunks. grid = (T/64, B, 8).
// ---------------------------------------------------------------------------
__global__ void av_kernel(const float* __restrict__ mean_w)
{
    const int t_tile = blockIdx.x;
    const int b      = blockIdx.y;
    const int chunk  = blockIdx.z;
    const int t0 = t_tile * 64;

    __shared__ float Ws[64][65];
    __shared__ float Vs[64][65];

    const int tx = threadIdx.x, ty = threadIdx.y;
    const int tid = ty * 16 + tx;

    float acc[4][4];
#pragma unroll
    for (int i = 0; i < 4; i++)
#pragma unroll
        for (int j = 0; j < 4; j++) acc[i][j] = 0.f;

    const int st_begin = chunk * 4;
    const int st_end   = min(chunk * 4 + 4, t_tile + 1);

    for (int st = st_begin; st < st_end; st++) {
        const int s0 = st * 64;
#pragma unroll
        for (int i = 0; i < 16; i++) {
            int idx = tid + i * 256;
            int r = idx >> 6, c = idx & 63;
            Ws[r][c] = mean_w[((size_t)b * T + t0 + r) * T + s0 + c];
            Vs[r][c] = g_V[((size_t)b * T + s0 + r) * D + c];
        }
        __syncthreads();
#pragma unroll 8
        for (int kk = 0; kk < 64; kk++) {
            float a[4], bb[4];
#pragma unroll
            for (int i = 0; i < 4; i++) a[i]  = Ws[ty * 4 + i][kk];
#pragma unroll
            for (int j = 0; j < 4; j++) bb[j] = Vs[kk][tx * 4 + j];
#pragma unroll
            for (int i = 0; i < 4; i++)
#pragma unroll
                for (int j = 0; j < 4; j++) acc[i][j] += a[i] * bb[j];
        }
        __syncthreads();
    }

    float* Cp = g_MHp + (size_t)chunk * B * T * D;
#pragma unroll
    for (int i = 0; i < 4; i++)
#pragma unroll
        for (int j = 0; j < 4; j++)
            Cp[((size_t)b * T + t0 + ty * 4 + i) * D + tx * 4 + j] = acc[i][j];
}

// ---------------------------------------------------------------------------
// Kernel 6: out = (sum of 8 AV partials) @ Wo + bo. grid = (H/64, B*T/64).
// ---------------------------------------------------------------------------
__global__ void out_kernel(const float* __restrict__ Wo,
                           const float* __restrict__ bo,
                           float* __restrict__ out)
{
    const int n0 = blockIdx.x * 64;
    const int m0 = blockIdx.y * 64;

    __shared__ float As[64][65];
    __shared__ float Bs[64][65];

    const int tx = threadIdx.x, ty = threadIdx.y;
    const int tid = ty * 16 + tx;

    const size_t N = (size_t)B * T * D;
#pragma unroll
    for (int i = 0; i < 16; i++) {
        int idx = tid + i * 256;
        int r = idx >> 6, c = idx & 63;
        size_t mi = (size_t)(m0 + r) * D + c;
        float v = 0.f;
#pragma unroll
        for (int p = 0; p < 8; p++) v += g_MHp[p * N + mi];
        As[r][c] = v;
        Bs[r][c] = Wo[(size_t)r * H + n0 + c];
    }
    __syncthreads();

    float acc[4][4];
#pragma unroll
    for (int i = 0; i < 4; i++)
#pragma unroll
        for (int j = 0; j < 4; j++) acc[i][j] = 0.f;

#pragma unroll 8
    for (int kk = 0; kk < 64; kk++) {
        float a[4], bb[4];
#pragma unroll
        for (int i = 0; i < 4; i++) a[i]  = As[ty * 4 + i][kk];
#pragma unroll
        for (int j = 0; j < 4; j++) bb[j] = Bs[kk][tx * 4 + j];
#pragma unroll
        for (int i = 0; i < 4; i++)
#pragma unroll
            for (int j = 0; j < 4; j++) acc[i][j] += a[i] * bb[j];
    }

#pragma unroll
    for (int i = 0; i < 4; i++)
#pragma unroll
        for (int j = 0; j < 4; j++)
            out[(size_t)(m0 + ty * 4 + i) * H + n0 + tx * 4 + j] =
                acc[i][j] + bo[n0 + tx * 4 + j];
}

// ---------------------------------------------------------------------------
extern "C" void kernel_launch(void* const* d_in, const int* in_sizes, int n_in,
                              void* d_out, int out_size)
{
    const float* x  = (const float*)d_in[0];
    const float* Wq = (const float*)d_in[1];
    const float* bq = (const float*)d_in[2];
    const float* Wk = (const float*)d_in[3];
    const float* bk = (const float*)d_in[4];
    const float* Wv = (const float*)d_in[5];
    const float* bv = (const float*)d_in[6];
    const float* Wo = (const float*)d_in[7];
    const float* bo = (const float*)d_in[8];

    float* out      = (float*)d_out;                 // [B,T,H]
    float* mean_out = out + (size_t)B * T * H;       // [B,T,T]

    dim3 blk16(16, 16);

    qkproj_bf16        <<<dim3(H / 128, (B * T) / 128, 2), 256>>>(x, Wq, bq, Wk, bk);
    vproj_kernel       <<<dim3((B * T) / 64, 4), blk16>>>(x, Wv);
    vsum_kernel        <<<(B * T * D) / 256, 256>>>(bv);
    scores_bf16        <<<dim3(T / 128, T / 128, NH * B), 256>>>();
    softmax_mean_kernel<<<B * T, 256>>>(mean_out);
    av_kernel          <<<dim3(T / 64, B, 8), blk16>>>(mean_out);
    out_kernel         <<<dim3(H / 64, (B * T) / 64), blk16>>>(Wo, bo, out);
}

// round 10
// speedup vs baseline: 1.4989x; 1.0363x over previous
#include <cuda_runtime.h>
#include <cuda_fp16.h>
#include <cuda_bf16.h>
#include <math.h>
#include <stdint.h>

#define B    2
#define T    2048
#define H    1024
#define NH   16
#define D    64
#define SCALE 0.125f   // D^-0.5

// ---------------- static device scratch (no dynamic allocation allowed) ----
// Q,K layout: [B*T, NH*D] row-major bf16 (row = b*T+t, col = n*64+d)
__device__ __nv_bfloat16 g_Qh[(size_t)B * T * H];   // 8 MB
__device__ __nv_bfloat16 g_Kh[(size_t)B * T * H];   // 8 MB
__device__ float  g_Vp[(size_t)4 * B * T * D];      // 4 MB V split-K partials
__device__ float  g_V[(size_t)B * T * D];           // 1 MB
__device__ __half g_Wh[(size_t)NH * B * T * T];     // 268 MB exp(score) fp16
__device__ float  g_RS[(size_t)NH * B * T * 16];    // 4 MB per-(row,s-tile) exp sums
__device__ float  g_MHp[(size_t)8 * B * T * D];     // 8 MB AV partials (8 chunks)

// ---------------------------------------------------------------------------
__device__ __forceinline__ uint32_t pack_bf2(float lo, float hi) {
    __nv_bfloat162 h = __floats2bfloat162_rn(lo, hi);
    return *(uint32_t*)&h;
}

__device__ __forceinline__ void mma_bf16(float* d, const uint32_t* a, const uint32_t* b) {
    asm volatile(
        "mma.sync.aligned.m16n8k16.row.col.f32.bf16.bf16.f32 "
        "{%0,%1,%2,%3}, {%4,%5,%6,%7}, {%8,%9}, {%0,%1,%2,%3};"
        : "+f"(d[0]), "+f"(d[1]), "+f"(d[2]), "+f"(d[3])
        : "r"(a[0]), "r"(a[1]), "r"(a[2]), "r"(a[3]), "r"(b[0]), "r"(b[1]));
}

__device__ __forceinline__ uint32_t smem_u32(const void* p) {
    uint32_t a;
    asm("{ .reg .u64 t; cvta.to.shared.u64 t, %1; cvt.u32.u64 %0, t; }"
        : "=r"(a) : "l"(p));
    return a;
}

__device__ __forceinline__ void ldsm_x4(uint32_t* r, uint32_t addr) {
    asm volatile("ldmatrix.sync.aligned.m8n8.x4.shared.b16 {%0,%1,%2,%3}, [%4];"
        : "=r"(r[0]), "=r"(r[1]), "=r"(r[2]), "=r"(r[3]) : "r"(addr));
}

// ---------------------------------------------------------------------------
// Kernel 1: batched Q/K projection, bf16 tensor cores, fp32 accumulate.
// (EXACT R6/R9 version — known good.)
// grid = (8, 32, 2)  z: 0->Q, 1->K
// ---------------------------------------------------------------------------
__global__ void __launch_bounds__(256)
qkproj_bf16(const float* __restrict__ x,
            const float* __restrict__ Wq, const float* __restrict__ bq,
            const float* __restrict__ Wk, const float* __restrict__ bk)
{
    const float* Wm    = blockIdx.z ? Wk : Wq;
    const float* bias  = blockIdx.z ? bk : bq;
    __nv_bfloat16* C   = blockIdx.z ? g_Kh : g_Qh;
    const int n0 = blockIdx.x * 128;
    const int m0 = blockIdx.y * 128;

    __shared__ __align__(16) uint32_t As2[2][128][20];
    __shared__ __align__(16) uint32_t Bs2[2][16][136];

    const int tid  = threadIdx.x;
    const int lane = tid & 31;
    const int wid  = tid >> 5;
    const int wm   = wid >> 2;
    const int wn   = wid & 3;
    const int fr   = lane >> 2;
    const int fc   = lane & 3;

    const int am = tid >> 1;
    const int ak = (tid & 1) * 16;
    const float* xrow = x + (size_t)(m0 + am) * H + ak;
    const int p  = tid >> 4;
    const int nn = (tid & 15) * 8;
    const int bcol = n0 + nn;
    const size_t bbase = (size_t)(bcol >> 6) * (H * D) + (size_t)(bcol & 63);

    float acc[4][4][4];
#pragma unroll
    for (int i = 0; i < 4; i++)
#pragma unroll
        for (int j = 0; j < 4; j++)
#pragma unroll
            for (int q = 0; q < 4; q++) acc[i][j][q] = 0.f;

    float4 a0, a1, a2, a3, blo0, blo1, bhi0, bhi1;

    a0 = *(const float4*)&xrow[0];
    a1 = *(const float4*)&xrow[4];
    a2 = *(const float4*)&xrow[8];
    a3 = *(const float4*)&xrow[12];
    blo0 = *(const float4*)&Wm[bbase + (size_t)(2 * p)     * D];
    blo1 = *(const float4*)&Wm[bbase + (size_t)(2 * p)     * D + 4];
    bhi0 = *(const float4*)&Wm[bbase + (size_t)(2 * p + 1) * D];
    bhi1 = *(const float4*)&Wm[bbase + (size_t)(2 * p + 1) * D + 4];
    {
        uint4 u;
        u.x = pack_bf2(a0.x, a0.y); u.y = pack_bf2(a0.z, a0.w);
        u.z = pack_bf2(a1.x, a1.y); u.w = pack_bf2(a1.z, a1.w);
        *(uint4*)&As2[0][am][ak / 2] = u;
        u.x = pack_bf2(a2.x, a2.y); u.y = pack_bf2(a2.z, a2.w);
        u.z = pack_bf2(a3.x, a3.y); u.w = pack_bf2(a3.z, a3.w);
        *(uint4*)&As2[0][am][ak / 2 + 4] = u;
        u.x = pack_bf2(blo0.x, bhi0.x); u.y = pack_bf2(blo0.y, bhi0.y);
        u.z = pack_bf2(blo0.z, bhi0.z); u.w = pack_bf2(blo0.w, bhi0.w);
        *(uint4*)&Bs2[0][p][nn] = u;
        u.x = pack_bf2(blo1.x, bhi1.x); u.y = pack_bf2(blo1.y, bhi1.y);
        u.z = pack_bf2(blo1.z, bhi1.z); u.w = pack_bf2(blo1.w, bhi1.w);
        *(uint4*)&Bs2[0][p][nn + 4] = u;
    }
    __syncthreads();

    const int NIT = H / 32;
    for (int it = 0; it < NIT; it++) {
        const int buf = it & 1;
        if (it < NIT - 1) {
            const int k0 = (it + 1) * 32;
            a0 = *(const float4*)&xrow[k0];
            a1 = *(const float4*)&xrow[k0 + 4];
            a2 = *(const float4*)&xrow[k0 + 8];
            a3 = *(const float4*)&xrow[k0 + 12];
            blo0 = *(const float4*)&Wm[bbase + (size_t)(k0 + 2 * p)     * D];
            blo1 = *(const float4*)&Wm[bbase + (size_t)(k0 + 2 * p)     * D + 4];
            bhi0 = *(const float4*)&Wm[bbase + (size_t)(k0 + 2 * p + 1) * D];
            bhi1 = *(const float4*)&Wm[bbase + (size_t)(k0 + 2 * p + 1) * D + 4];
        }
#pragma unroll
        for (int ks = 0; ks < 2; ks++) {
            uint32_t af[4][4], bf[4][2];
#pragma unroll
            for (int tm = 0; tm < 4; tm++) {
                const int mb = wm * 64 + tm * 16;
                af[tm][0] = As2[buf][mb + fr][ks * 8 + fc];
                af[tm][1] = As2[buf][mb + fr + 8][ks * 8 + fc];
                af[tm][2] = As2[buf][mb + fr][ks * 8 + fc + 4];
                af[tm][3] = As2[buf][mb + fr + 8][ks * 8 + fc + 4];
            }
#pragma unroll
            for (int tn = 0; tn < 4; tn++) {
                const int nb = wn * 32 + tn * 8 + fr;
                bf[tn][0] = Bs2[buf][ks * 8 + fc][nb];
                bf[tn][1] = Bs2[buf][ks * 8 + fc + 4][nb];
            }
#pragma unroll
            for (int tm = 0; tm < 4; tm++)
#pragma unroll
                for (int tn = 0; tn < 4; tn++)
                    mma_bf16(acc[tm][tn], af[tm], bf[tn]);
        }
        if (it < NIT - 1) {
            const int nb2 = (it & 1) ^ 1;
            uint4 u;
            u.x = pack_bf2(a0.x, a0.y); u.y = pack_bf2(a0.z, a0.w);
            u.z = pack_bf2(a1.x, a1.y); u.w = pack_bf2(a1.z, a1.w);
            *(uint4*)&As2[nb2][am][ak / 2] = u;
            u.x = pack_bf2(a2.x, a2.y); u.y = pack_bf2(a2.z, a2.w);
            u.z = pack_bf2(a3.x, a3.y); u.w = pack_bf2(a3.z, a3.w);
            *(uint4*)&As2[nb2][am][ak / 2 + 4] = u;
            u.x = pack_bf2(blo0.x, bhi0.x); u.y = pack_bf2(blo0.y, bhi0.y);
            u.z = pack_bf2(blo0.z, bhi0.z); u.w = pack_bf2(blo0.w, bhi0.w);
            *(uint4*)&Bs2[nb2][p][nn] = u;
            u.x = pack_bf2(blo1.x, bhi1.x); u.y = pack_bf2(blo1.y, bhi1.y);
            u.z = pack_bf2(blo1.z, bhi1.z); u.w = pack_bf2(blo1.w, bhi1.w);
            *(uint4*)&Bs2[nb2][p][nn + 4] = u;
        }
        __syncthreads();
    }

#pragma unroll
    for (int tm = 0; tm < 4; tm++)
#pragma unroll
        for (int tn = 0; tn < 4; tn++) {
            const int row = m0 + wm * 64 + tm * 16 + fr;
            const int col = n0 + wn * 32 + tn * 8 + 2 * fc;
            const float b0 = bias[col], b1 = bias[col + 1];
            __nv_bfloat162 o;
            o = __floats2bfloat162_rn(acc[tm][tn][0] + b0, acc[tm][tn][1] + b1);
            *(__nv_bfloat162*)&C[(size_t)row * H + col] = o;
            o = __floats2bfloat162_rn(acc[tm][tn][2] + b0, acc[tm][tn][3] + b1);
            *(__nv_bfloat162*)&C[(size_t)(row + 8) * H + col] = o;
        }
}

// ---------------------------------------------------------------------------
// Kernel 2: V projection, split-K fp32. grid = (B*T/64, 4).
// ---------------------------------------------------------------------------
__global__ void vproj_kernel(const float* __restrict__ x,
                             const float* __restrict__ Wv)
{
    const int m0 = blockIdx.x * 64;
    const int kbase = blockIdx.y * (H / 4);
    float* Cp = g_Vp + (size_t)blockIdx.y * B * T * D;

    __shared__ float As[64][17];
    __shared__ float Bs[16][65];

    const int tx = threadIdx.x, ty = threadIdx.y;
    const int tid = ty * 16 + tx;

    float acc[4][4];
#pragma unroll
    for (int i = 0; i < 4; i++)
#pragma unroll
        for (int j = 0; j < 4; j++) acc[i][j] = 0.f;

    for (int kc = 0; kc < H / 4; kc += 16) {
        const int k0 = kbase + kc;
#pragma unroll
        for (int i = 0; i < 4; i++) {
            int idx = tid + i * 256;
            int r = idx >> 4, c = idx & 15;
            As[r][c] = x[(size_t)(m0 + r) * H + k0 + c];
        }
#pragma unroll
        for (int i = 0; i < 4; i++) {
            int idx = tid + i * 256;
            int r = idx >> 6, c = idx & 63;
            Bs[r][c] = Wv[(size_t)(k0 + r) * D + c];
        }
        __syncthreads();
#pragma unroll
        for (int kk = 0; kk < 16; kk++) {
            float a[4], bb[4];
#pragma unroll
            for (int i = 0; i < 4; i++) a[i]  = As[ty * 4 + i][kk];
#pragma unroll
            for (int j = 0; j < 4; j++) bb[j] = Bs[kk][tx * 4 + j];
#pragma unroll
            for (int i = 0; i < 4; i++)
#pragma unroll
                for (int j = 0; j < 4; j++) acc[i][j] += a[i] * bb[j];
        }
        __syncthreads();
    }
#pragma unroll
    for (int i = 0; i < 4; i++)
#pragma unroll
        for (int j = 0; j < 4; j++)
            Cp[(size_t)(m0 + ty * 4 + i) * D + tx * 4 + j] = acc[i][j];
}

// vsum: g_V = sum of 4 partials + bias. grid = B*T*D/256, block 256.
__global__ void vsum_kernel(const float* __restrict__ bv)
{
    const size_t i = (size_t)blockIdx.x * 256 + threadIdx.x;
    const size_t N = (size_t)B * T * D;
    g_V[i] = g_Vp[i] + g_Vp[N + i] + g_Vp[2 * N + i] + g_Vp[3 * N + i]
           + bv[i & 63];
}

// ---------------------------------------------------------------------------
// Kernel 3: scores via bf16 mma, ldmatrix fragment loads, coalesced fp16
// epilogue through smem. grid = (16,16,NH*B), z = n*2+b.
// ---------------------------------------------------------------------------
__global__ void __launch_bounds__(256)
scores_bf16()
{
    const int st = blockIdx.x;
    const int tt = blockIdx.y;
    if (st > tt) return;
    const int z = blockIdx.z;
    const int n = z >> 1, b = z & 1;

    const __nv_bfloat16* Qb = g_Qh + (size_t)b * T * H + (size_t)n * D;
    const __nv_bfloat16* Kb = g_Kh + (size_t)b * T * H + (size_t)n * D;
    __half* Wp = g_Wh + (size_t)z * T * T;

    const int t0 = tt * 128, s0 = st * 128;

    // union: Q/K tiles during mainloop; half2 result tile during epilogue
    __shared__ __align__(16) union {
        struct { uint32_t Q[128][36]; uint32_t K[128][36]; } qk;  // 36.9 KB
        uint32_t S[128][68];                                      // 34.8 KB
    } sm;
    __shared__ float rs[128][4];

    const int tid  = threadIdx.x;
    const int lane = tid & 31;
    const int wid  = tid >> 5;
    const int wm   = wid >> 2;
    const int wn   = wid & 3;
    const int fr   = lane >> 2;
    const int fc   = lane & 3;

    // ---- stage Q/K tiles (D=64 bf16 per row) ----
    const int sr = tid >> 1;
    const int sc = (tid & 1) * 32;
#pragma unroll
    for (int u = 0; u < 4; u++) {
        uint4 q4 = *(const uint4*)&Qb[(size_t)(t0 + sr) * H + sc + u * 8];
        uint4 k4 = *(const uint4*)&Kb[(size_t)(s0 + sr) * H + sc + u * 8];
        *(uint4*)&sm.qk.Q[sr][sc / 2 + u * 4] = q4;
        *(uint4*)&sm.qk.K[sr][sc / 2 + u * 4] = k4;
    }
    __syncthreads();

    // ---- ldmatrix base addresses ----
    // A (16x16 tile, x4): lane -> row (lane&15), k-word off ((lane>>4)*4)
    uint32_t aAddr[4];
    {
        const int lr = lane & 15, lk = (lane >> 4) * 4;
#pragma unroll
        for (int tm = 0; tm < 4; tm++)
            aAddr[tm] = smem_u32(&sm.qk.Q[wm * 64 + tm * 16 + lr][lk]);
    }
    // B (two n8xk16 tiles per x4): lane -> row ((lane>>4)*8 + (lane&7)),
    // k-word off (((lane>>3)&1)*4)
    uint32_t bAddr[2];
    {
        const int br = (lane >> 4) * 8 + (lane & 7);
        const int bk = ((lane >> 3) & 1) * 4;
#pragma unroll
        for (int tp = 0; tp < 2; tp++)
            bAddr[tp] = smem_u32(&sm.qk.K[wn * 32 + tp * 16 + br][bk]);
    }

    float acc[4][4][4];
#pragma unroll
    for (int i = 0; i < 4; i++)
#pragma unroll
        for (int j = 0; j < 4; j++)
#pragma unroll
            for (int q = 0; q < 4; q++) acc[i][j][q] = 0.f;

#pragma unroll
    for (int ks = 0; ks < 4; ks++) {          // 4 x k16 = D=64
        uint32_t af[4][4], bq0[4], bq1[4];
#pragma unroll
        for (int tm = 0; tm < 4; tm++)
            ldsm_x4(af[tm], aAddr[tm] + ks * 32);
        ldsm_x4(bq0, bAddr[0] + ks * 32);      // r0,r1 = tn0; r2,r3 = tn1
        ldsm_x4(bq1, bAddr[1] + ks * 32);      // r0,r1 = tn2; r2,r3 = tn3
        uint32_t bf[4][2];
        bf[0][0] = bq0[0]; bf[0][1] = bq0[1];
        bf[1][0] = bq0[2]; bf[1][1] = bq0[3];
        bf[2][0] = bq1[0]; bf[2][1] = bq1[1];
        bf[3][0] = bq1[2]; bf[3][1] = bq1[3];
#pragma unroll
        for (int tm = 0; tm < 4; tm++)
#pragma unroll
            for (int tn = 0; tn < 4; tn++)
                mma_bf16(acc[tm][tn], af[tm], bf[tn]);
    }

    // all warps done reading Q/K smem before the union is repurposed
    __syncthreads();

    // ---- epilogue: exp + mask into smem half2 tile; per-row partial sums --
    const bool diag = (st == tt);
#pragma unroll
    for (int tm = 0; tm < 4; tm++)
#pragma unroll
        for (int rq = 0; rq < 2; rq++) {
            const int rloc = wm * 64 + tm * 16 + fr + rq * 8;
            const int t = t0 + rloc;
            float rsum = 0.f;
#pragma unroll
            for (int tn = 0; tn < 4; tn++) {
                const int s = s0 + wn * 32 + tn * 8 + 2 * fc;
                float e0 = __expf(acc[tm][tn][rq * 2 + 0] * SCALE);
                float e1 = __expf(acc[tm][tn][rq * 2 + 1] * SCALE);
                if (diag) {
                    if (s     > t) e0 = 0.f;
                    if (s + 1 > t) e1 = 0.f;
                }
                rsum += e0 + e1;
                __half2 h = __floats2half2_rn(e0, e1);
                sm.S[rloc][wn * 16 + tn * 4 + fc] = *(uint32_t*)&h;
            }
            rsum += __shfl_xor_sync(0xffffffffu, rsum, 1);
            rsum += __shfl_xor_sync(0xffffffffu, rsum, 2);
            if (fc == 0) rs[rloc][wn] = rsum;
        }
    __syncthreads();

    // ---- coalesced store: each pass writes 16 rows x 128 halves dense ----
    const int rr0 = tid >> 4;            // 0..15
    const int cw  = (tid & 15) * 4;      // word col (8 halves)
#pragma unroll
    for (int i = 0; i < 8; i++) {
        const int rr = rr0 + i * 16;
        uint4 v = *(const uint4*)&sm.S[rr][cw];
        *(uint4*)&Wp[(size_t)(t0 + rr) * T + s0 + cw * 2] = v;
    }

    if (tid < 128) {
        float v = rs[tid][0] + rs[tid][1] + rs[tid][2] + rs[tid][3];
        g_RS[((size_t)z * T + t0 + tid) * 16 + st] = v;
    }
}

// ---------------------------------------------------------------------------
// Kernel 4: streaming mean-of-softmax. One block per (b,t), 256 threads.
// ---------------------------------------------------------------------------
__global__ void __launch_bounds__(256)
softmax_mean_kernel(float* __restrict__ out_mean)
{
    const int row = blockIdx.x;   // b*T + t
    const int b = row >> 11;
    const int t = row & 2047;
    const int tid = threadIdx.x;

    const int nst = (t >> 7) + 1;
    const int L   = nst * 128;

    __shared__ float sinv[NH];
    if (tid < NH) {
        const float* p = g_RS + ((size_t)(tid * B + b) * T + t) * 16;
        float s = 0.f;
        for (int i = 0; i < nst; i++) s += p[i];
        sinv[tid] = (1.0f / NH) / s;
    }
    __syncthreads();

    const int c0 = tid * 8;
    float acc[8];
#pragma unroll
    for (int i = 0; i < 8; i++) acc[i] = 0.f;

    if (c0 < L) {
        const size_t rowoff = ((size_t)b * T + t) * T + c0;
#pragma unroll
        for (int n = 0; n < NH; n++) {
            const __half* p = g_Wh + (size_t)n * (B * (size_t)T * T) + rowoff;
            uint4 u = *(const uint4*)p;
            const float w = sinv[n];
            float2 f;
            f = __half22float2(*(__half2*)&u.x); acc[0] += f.x * w; acc[1] += f.y * w;
            f = __half22float2(*((__half2*)&u.x + 1)); acc[2] += f.x * w; acc[3] += f.y * w;
            f = __half22float2(*(__half2*)&u.z); acc[4] += f.x * w; acc[5] += f.y * w;
            f = __half22float2(*((__half2*)&u.z + 1)); acc[6] += f.x * w; acc[7] += f.y * w;
        }
    }

    float* mrow = out_mean + (size_t)row * T + c0;
    *(float4*)&mrow[0] = make_float4(acc[0], acc[1], acc[2], acc[3]);
    *(float4*)&mrow[4] = make_float4(acc[4], acc[5], acc[6], acc[7]);
}

// ---------------------------------------------------------------------------
// Kernel 5: AV via head-mean identity, 8 s-chunks. grid = (T/64, B, 8).
// ---------------------------------------------------------------------------
__global__ void av_kernel(const float* __restrict__ mean_w)
{
    const int t_tile = blockIdx.x;
    const int b      = blockIdx.y;
    const int chunk  = blockIdx.z;
    const int t0 = t_tile * 64;

    __shared__ float Ws[64][65];
    __shared__ float Vs[64][65];

    const int tx = threadIdx.x, ty = threadIdx.y;
    const int tid = ty * 16 + tx;

    float acc[4][4];
#pragma unroll
    for (int i = 0; i < 4; i++)
#pragma unroll
        for (int j = 0; j < 4; j++) acc[i][j] = 0.f;

    const int st_begin = chunk * 4;
    const int st_end   = min(chunk * 4 + 4, t_tile + 1);

    for (int st = st_begin; st < st_end; st++) {
        const int s0 = st * 64;
#pragma unroll
        for (int i = 0; i < 16; i++) {
            int idx = tid + i * 256;
            int r = idx >> 6, c = idx & 63;
            Ws[r][c] = mean_w[((size_t)b * T + t0 + r) * T + s0 + c];
            Vs[r][c] = g_V[((size_t)b * T + s0 + r) * D + c];
        }
        __syncthreads();
#pragma unroll 8
        for (int kk = 0; kk < 64; kk++) {
            float a[4], bb[4];
#pragma unroll
            for (int i = 0; i < 4; i++) a[i]  = Ws[ty * 4 + i][kk];
#pragma unroll
            for (int j = 0; j < 4; j++) bb[j] = Vs[kk][tx * 4 + j];
#pragma unroll
            for (int i = 0; i < 4; i++)
#pragma unroll
                for (int j = 0; j < 4; j++) acc[i][j] += a[i] * bb[j];
        }
        __syncthreads();
    }

    float* Cp = g_MHp + (size_t)chunk * B * T * D;
#pragma unroll
    for (int i = 0; i < 4; i++)
#pragma unroll
        for (int j = 0; j < 4; j++)
            Cp[((size_t)b * T + t0 + ty * 4 + i) * D + tx * 4 + j] = acc[i][j];
}

// ---------------------------------------------------------------------------
// Kernel 6: out = (sum of 8 AV partials) @ Wo + bo. grid = (H/64, B*T/64).
// ---------------------------------------------------------------------------
__global__ void out_kernel(const float* __restrict__ Wo,
                           const float* __restrict__ bo,
                           float* __restrict__ out)
{
    const int n0 = blockIdx.x * 64;
    const int m0 = blockIdx.y * 64;

    __shared__ float As[64][65];
    __shared__ float Bs[64][65];

    const int tx = threadIdx.x, ty = threadIdx.y;
    const int tid = ty * 16 + tx;

    const size_t N = (size_t)B * T * D;
#pragma unroll
    for (int i = 0; i < 16; i++) {
        int idx = tid + i * 256;
        int r = idx >> 6, c = idx & 63;
        size_t mi = (size_t)(m0 + r) * D + c;
        float v = 0.f;
#pragma unroll
        for (int p = 0; p < 8; p++) v += g_MHp[p * N + mi];
        As[r][c] = v;
        Bs[r][c] = Wo[(size_t)r * H + n0 + c];
    }
    __syncthreads();

    float acc[4][4];
#pragma unroll
    for (int i = 0; i < 4; i++)
#pragma unroll
        for (int j = 0; j < 4; j++) acc[i][j] = 0.f;

#pragma unroll 8
    for (int kk = 0; kk < 64; kk++) {
        float a[4], bb[4];
#pragma unroll
        for (int i = 0; i < 4; i++) a[i]  = As[ty * 4 + i][kk];
#pragma unroll
        for (int j = 0; j < 4; j++) bb[j] = Bs[kk][tx * 4 + j];
#pragma unroll
        for (int i = 0; i < 4; i++)
#pragma unroll
            for (int j = 0; j < 4; j++) acc[i][j] += a[i] * bb[j];
    }

#pragma unroll
    for (int i = 0; i < 4; i++)
#pragma unroll
        for (int j = 0; j < 4; j++)
            out[(size_t)(m0 + ty * 4 + i) * H + n0 + tx * 4 + j] =
                acc[i][j] + bo[n0 + tx * 4 + j];
}

// ---------------------------------------------------------------------------
extern "C" void kernel_launch(void* const* d_in, const int* in_sizes, int n_in,
                              void* d_out, int out_size)
{
    const float* x  = (const float*)d_in[0];
    const float* Wq = (const float*)d_in[1];
    const float* bq = (const float*)d_in[2];
    const float* Wk = (const float*)d_in[3];
    const float* bk = (const float*)d_in[4];
    const float* Wv = (const float*)d_in[5];
    const float* bv = (const float*)d_in[6];
    const float* Wo = (const float*)d_in[7];
    const float* bo = (const float*)d_in[8];

    float* out      = (float*)d_out;                 // [B,T,H]
    float* mean_out = out + (size_t)B * T * H;       // [B,T,T]

    dim3 blk16(16, 16);

    qkproj_bf16        <<<dim3(H / 128, (B * T) / 128, 2), 256>>>(x, Wq, bq, Wk, bk);
    vproj_kernel       <<<dim3((B * T) / 64, 4), blk16>>>(x, Wv);
    vsum_kernel        <<<(B * T * D) / 256, 256>>>(bv);
    scores_bf16        <<<dim3(T / 128, T / 128, NH * B), 256>>>();
    softmax_mean_kernel<<<B * T, 256>>>(mean_out);
    av_kernel          <<<dim3(T / 64, B, 8), blk16>>>(mean_out);
    out_kernel         <<<dim3(H / 64, (B * T) / 64), blk16>>>(Wo, bo, out);
}

// round 11
// speedup vs baseline: 1.5362x; 1.0249x over previous
#include <cuda_runtime.h>
#include <cuda_fp16.h>
#include <cuda_bf16.h>
#include <math.h>
#include <stdint.h>

#define B    2
#define T    2048
#define H    1024
#define NH   16
#define D    64
#define SCALE 0.125f   // D^-0.5

// ---------------- static device scratch (no dynamic allocation allowed) ----
// Q,K layout: [B*T, NH*D] row-major bf16 (row = b*T+t, col = n*64+d)
__device__ __nv_bfloat16 g_Qh[(size_t)B * T * H];   // 8 MB
__device__ __nv_bfloat16 g_Kh[(size_t)B * T * H];   // 8 MB
__device__ float  g_Vp[(size_t)4 * B * T * D];      // 4 MB V split-K partials
__device__ float  g_V[(size_t)B * T * D];           // 1 MB
__device__ __half g_Wh[(size_t)NH * B * T * T];     // 268 MB exp(score) fp16
__device__ float  g_RS[(size_t)NH * B * T * 16];    // 4 MB per-(row,s-tile) exp sums
__device__ float  g_MHp[(size_t)8 * B * T * D];     // 8 MB AV partials (8 chunks)
__device__ float  g_MH[(size_t)B * T * D];          // 1 MB reduced mean_head

// ---------------------------------------------------------------------------
__device__ __forceinline__ uint32_t pack_bf2(float lo, float hi) {
    __nv_bfloat162 h = __floats2bfloat162_rn(lo, hi);
    return *(uint32_t*)&h;
}

__device__ __forceinline__ void mma_bf16(float* d, const uint32_t* a, const uint32_t* b) {
    asm volatile(
        "mma.sync.aligned.m16n8k16.row.col.f32.bf16.bf16.f32 "
        "{%0,%1,%2,%3}, {%4,%5,%6,%7}, {%8,%9}, {%0,%1,%2,%3};"
        : "+f"(d[0]), "+f"(d[1]), "+f"(d[2]), "+f"(d[3])
        : "r"(a[0]), "r"(a[1]), "r"(a[2]), "r"(a[3]), "r"(b[0]), "r"(b[1]));
}

__device__ __forceinline__ uint32_t smem_u32(const void* p) {
    uint32_t a;
    asm("{ .reg .u64 t; cvta.to.shared.u64 t, %1; cvt.u32.u64 %0, t; }"
        : "=r"(a) : "l"(p));
    return a;
}

__device__ __forceinline__ void ldsm_x4(uint32_t* r, uint32_t addr) {
    asm volatile("ldmatrix.sync.aligned.m8n8.x4.shared.b16 {%0,%1,%2,%3}, [%4];"
        : "=r"(r[0]), "=r"(r[1]), "=r"(r[2]), "=r"(r[3]) : "r"(addr));
}

// ---------------------------------------------------------------------------
// Kernel 1: batched Q/K projection, bf16 tensor cores, fp32 accumulate.
// (EXACT R6/R9 version — known good, ~at mma.sync issue ceiling.)
// grid = (8, 32, 2)  z: 0->Q, 1->K
// ---------------------------------------------------------------------------
__global__ void __launch_bounds__(256)
qkproj_bf16(const float* __restrict__ x,
            const float* __restrict__ Wq, const float* __restrict__ bq,
            const float* __restrict__ Wk, const float* __restrict__ bk)
{
    const float* Wm    = blockIdx.z ? Wk : Wq;
    const float* bias  = blockIdx.z ? bk : bq;
    __nv_bfloat16* C   = blockIdx.z ? g_Kh : g_Qh;
    const int n0 = blockIdx.x * 128;
    const int m0 = blockIdx.y * 128;

    __shared__ __align__(16) uint32_t As2[2][128][20];
    __shared__ __align__(16) uint32_t Bs2[2][16][136];

    const int tid  = threadIdx.x;
    const int lane = tid & 31;
    const int wid  = tid >> 5;
    const int wm   = wid >> 2;
    const int wn   = wid & 3;
    const int fr   = lane >> 2;
    const int fc   = lane & 3;

    const int am = tid >> 1;
    const int ak = (tid & 1) * 16;
    const float* xrow = x + (size_t)(m0 + am) * H + ak;
    const int p  = tid >> 4;
    const int nn = (tid & 15) * 8;
    const int bcol = n0 + nn;
    const size_t bbase = (size_t)(bcol >> 6) * (H * D) + (size_t)(bcol & 63);

    float acc[4][4][4];
#pragma unroll
    for (int i = 0; i < 4; i++)
#pragma unroll
        for (int j = 0; j < 4; j++)
#pragma unroll
            for (int q = 0; q < 4; q++) acc[i][j][q] = 0.f;

    float4 a0, a1, a2, a3, blo0, blo1, bhi0, bhi1;

    a0 = *(const float4*)&xrow[0];
    a1 = *(const float4*)&xrow[4];
    a2 = *(const float4*)&xrow[8];
    a3 = *(const float4*)&xrow[12];
    blo0 = *(const float4*)&Wm[bbase + (size_t)(2 * p)     * D];
    blo1 = *(const float4*)&Wm[bbase + (size_t)(2 * p)     * D + 4];
    bhi0 = *(const float4*)&Wm[bbase + (size_t)(2 * p + 1) * D];
    bhi1 = *(const float4*)&Wm[bbase + (size_t)(2 * p + 1) * D + 4];
    {
        uint4 u;
        u.x = pack_bf2(a0.x, a0.y); u.y = pack_bf2(a0.z, a0.w);
        u.z = pack_bf2(a1.x, a1.y); u.w = pack_bf2(a1.z, a1.w);
        *(uint4*)&As2[0][am][ak / 2] = u;
        u.x = pack_bf2(a2.x, a2.y); u.y = pack_bf2(a2.z, a2.w);
        u.z = pack_bf2(a3.x, a3.y); u.w = pack_bf2(a3.z, a3.w);
        *(uint4*)&As2[0][am][ak / 2 + 4] = u;
        u.x = pack_bf2(blo0.x, bhi0.x); u.y = pack_bf2(blo0.y, bhi0.y);
        u.z = pack_bf2(blo0.z, bhi0.z); u.w = pack_bf2(blo0.w, bhi0.w);
        *(uint4*)&Bs2[0][p][nn] = u;
        u.x = pack_bf2(blo1.x, bhi1.x); u.y = pack_bf2(blo1.y, bhi1.y);
        u.z = pack_bf2(blo1.z, bhi1.z); u.w = pack_bf2(blo1.w, bhi1.w);
        *(uint4*)&Bs2[0][p][nn + 4] = u;
    }
    __syncthreads();

    const int NIT = H / 32;
    for (int it = 0; it < NIT; it++) {
        const int buf = it & 1;
        if (it < NIT - 1) {
            const int k0 = (it + 1) * 32;
            a0 = *(const float4*)&xrow[k0];
            a1 = *(const float4*)&xrow[k0 + 4];
            a2 = *(const float4*)&xrow[k0 + 8];
            a3 = *(const float4*)&xrow[k0 + 12];
            blo0 = *(const float4*)&Wm[bbase + (size_t)(k0 + 2 * p)     * D];
            blo1 = *(const float4*)&Wm[bbase + (size_t)(k0 + 2 * p)     * D + 4];
            bhi0 = *(const float4*)&Wm[bbase + (size_t)(k0 + 2 * p + 1) * D];
            bhi1 = *(const float4*)&Wm[bbase + (size_t)(k0 + 2 * p + 1) * D + 4];
        }
#pragma unroll
        for (int ks = 0; ks < 2; ks++) {
            uint32_t af[4][4], bf[4][2];
#pragma unroll
            for (int tm = 0; tm < 4; tm++) {
                const int mb = wm * 64 + tm * 16;
                af[tm][0] = As2[buf][mb + fr][ks * 8 + fc];
                af[tm][1] = As2[buf][mb + fr + 8][ks * 8 + fc];
                af[tm][2] = As2[buf][mb + fr][ks * 8 + fc + 4];
                af[tm][3] = As2[buf][mb + fr + 8][ks * 8 + fc + 4];
            }
#pragma unroll
            for (int tn = 0; tn < 4; tn++) {
                const int nb = wn * 32 + tn * 8 + fr;
                bf[tn][0] = Bs2[buf][ks * 8 + fc][nb];
                bf[tn][1] = Bs2[buf][ks * 8 + fc + 4][nb];
            }
#pragma unroll
            for (int tm = 0; tm < 4; tm++)
#pragma unroll
                for (int tn = 0; tn < 4; tn++)
                    mma_bf16(acc[tm][tn], af[tm], bf[tn]);
        }
        if (it < NIT - 1) {
            const int nb2 = (it & 1) ^ 1;
            uint4 u;
            u.x = pack_bf2(a0.x, a0.y); u.y = pack_bf2(a0.z, a0.w);
            u.z = pack_bf2(a1.x, a1.y); u.w = pack_bf2(a1.z, a1.w);
            *(uint4*)&As2[nb2][am][ak / 2] = u;
            u.x = pack_bf2(a2.x, a2.y); u.y = pack_bf2(a2.z, a2.w);
            u.z = pack_bf2(a3.x, a3.y); u.w = pack_bf2(a3.z, a3.w);
            *(uint4*)&As2[nb2][am][ak / 2 + 4] = u;
            u.x = pack_bf2(blo0.x, bhi0.x); u.y = pack_bf2(blo0.y, bhi0.y);
            u.z = pack_bf2(blo0.z, bhi0.z); u.w = pack_bf2(blo0.w, bhi0.w);
            *(uint4*)&Bs2[nb2][p][nn] = u;
            u.x = pack_bf2(blo1.x, bhi1.x); u.y = pack_bf2(blo1.y, bhi1.y);
            u.z = pack_bf2(blo1.z, bhi1.z); u.w = pack_bf2(blo1.w, bhi1.w);
            *(uint4*)&Bs2[nb2][p][nn + 4] = u;
        }
        __syncthreads();
    }

#pragma unroll
    for (int tm = 0; tm < 4; tm++)
#pragma unroll
        for (int tn = 0; tn < 4; tn++) {
            const int row = m0 + wm * 64 + tm * 16 + fr;
            const int col = n0 + wn * 32 + tn * 8 + 2 * fc;
            const float b0 = bias[col], b1 = bias[col + 1];
            __nv_bfloat162 o;
            o = __floats2bfloat162_rn(acc[tm][tn][0] + b0, acc[tm][tn][1] + b1);
            *(__nv_bfloat162*)&C[(size_t)row * H + col] = o;
            o = __floats2bfloat162_rn(acc[tm][tn][2] + b0, acc[tm][tn][3] + b1);
            *(__nv_bfloat162*)&C[(size_t)(row + 8) * H + col] = o;
        }
}

// ---------------------------------------------------------------------------
// Kernel 2: V projection, split-K fp32. grid = (B*T/64, 4).
// ---------------------------------------------------------------------------
__global__ void vproj_kernel(const float* __restrict__ x,
                             const float* __restrict__ Wv)
{
    const int m0 = blockIdx.x * 64;
    const int kbase = blockIdx.y * (H / 4);
    float* Cp = g_Vp + (size_t)blockIdx.y * B * T * D;

    __shared__ float As[64][17];
    __shared__ float Bs[16][65];

    const int tx = threadIdx.x, ty = threadIdx.y;
    const int tid = ty * 16 + tx;

    float acc[4][4];
#pragma unroll
    for (int i = 0; i < 4; i++)
#pragma unroll
        for (int j = 0; j < 4; j++) acc[i][j] = 0.f;

    for (int kc = 0; kc < H / 4; kc += 16) {
        const int k0 = kbase + kc;
#pragma unroll
        for (int i = 0; i < 4; i++) {
            int idx = tid + i * 256;
            int r = idx >> 4, c = idx & 15;
            As[r][c] = x[(size_t)(m0 + r) * H + k0 + c];
        }
#pragma unroll
        for (int i = 0; i < 4; i++) {
            int idx = tid + i * 256;
            int r = idx >> 6, c = idx & 63;
            Bs[r][c] = Wv[(size_t)(k0 + r) * D + c];
        }
        __syncthreads();
#pragma unroll
        for (int kk = 0; kk < 16; kk++) {
            float a[4], bb[4];
#pragma unroll
            for (int i = 0; i < 4; i++) a[i]  = As[ty * 4 + i][kk];
#pragma unroll
            for (int j = 0; j < 4; j++) bb[j] = Bs[kk][tx * 4 + j];
#pragma unroll
            for (int i = 0; i < 4; i++)
#pragma unroll
                for (int j = 0; j < 4; j++) acc[i][j] += a[i] * bb[j];
        }
        __syncthreads();
    }
#pragma unroll
    for (int i = 0; i < 4; i++)
#pragma unroll
        for (int j = 0; j < 4; j++)
            Cp[(size_t)(m0 + ty * 4 + i) * D + tx * 4 + j] = acc[i][j];
}

// vsum: g_V = sum of 4 partials + bias. grid = B*T*D/256, block 256.
__global__ void vsum_kernel(const float* __restrict__ bv)
{
    const size_t i = (size_t)blockIdx.x * 256 + threadIdx.x;
    const size_t N = (size_t)B * T * D;
    g_V[i] = g_Vp[i] + g_Vp[N + i] + g_Vp[2 * N + i] + g_Vp[3 * N + i]
           + bv[i & 63];
}

// ---------------------------------------------------------------------------
// Kernel 3: scores via bf16 mma, ldmatrix fragment loads, coalesced fp16
// epilogue through smem. grid = (16,16,NH*B), z = n*2+b.
// ---------------------------------------------------------------------------
__global__ void __launch_bounds__(256)
scores_bf16()
{
    const int st = blockIdx.x;
    const int tt = blockIdx.y;
    if (st > tt) return;
    const int z = blockIdx.z;
    const int n = z >> 1, b = z & 1;

    const __nv_bfloat16* Qb = g_Qh + (size_t)b * T * H + (size_t)n * D;
    const __nv_bfloat16* Kb = g_Kh + (size_t)b * T * H + (size_t)n * D;
    __half* Wp = g_Wh + (size_t)z * T * T;

    const int t0 = tt * 128, s0 = st * 128;

    // union: Q/K tiles during mainloop; half2 result tile during epilogue
    __shared__ __align__(16) union {
        struct { uint32_t Q[128][36]; uint32_t K[128][36]; } qk;  // 36.9 KB
        uint32_t S[128][68];                                      // 34.8 KB
    } sm;
    __shared__ float rs[128][4];

    const int tid  = threadIdx.x;
    const int lane = tid & 31;
    const int wid  = tid >> 5;
    const int wm   = wid >> 2;
    const int wn   = wid & 3;
    const int fr   = lane >> 2;
    const int fc   = lane & 3;

    // ---- stage Q/K tiles (D=64 bf16 per row) ----
    const int sr = tid >> 1;
    const int sc = (tid & 1) * 32;
#pragma unroll
    for (int u = 0; u < 4; u++) {
        uint4 q4 = *(const uint4*)&Qb[(size_t)(t0 + sr) * H + sc + u * 8];
        uint4 k4 = *(const uint4*)&Kb[(size_t)(s0 + sr) * H + sc + u * 8];
        *(uint4*)&sm.qk.Q[sr][sc / 2 + u * 4] = q4;
        *(uint4*)&sm.qk.K[sr][sc / 2 + u * 4] = k4;
    }
    __syncthreads();

    // ---- ldmatrix base addresses ----
    uint32_t aAddr[4];
    {
        const int lr = lane & 15, lk = (lane >> 4) * 4;
#pragma unroll
        for (int tm = 0; tm < 4; tm++)
            aAddr[tm] = smem_u32(&sm.qk.Q[wm * 64 + tm * 16 + lr][lk]);
    }
    uint32_t bAddr[2];
    {
        const int br = (lane >> 4) * 8 + (lane & 7);
        const int bk = ((lane >> 3) & 1) * 4;
#pragma unroll
        for (int tp = 0; tp < 2; tp++)
            bAddr[tp] = smem_u32(&sm.qk.K[wn * 32 + tp * 16 + br][bk]);
    }

    float acc[4][4][4];
#pragma unroll
    for (int i = 0; i < 4; i++)
#pragma unroll
        for (int j = 0; j < 4; j++)
#pragma unroll
            for (int q = 0; q < 4; q++) acc[i][j][q] = 0.f;

#pragma unroll
    for (int ks = 0; ks < 4; ks++) {          // 4 x k16 = D=64
        uint32_t af[4][4], bq0[4], bq1[4];
#pragma unroll
        for (int tm = 0; tm < 4; tm++)
            ldsm_x4(af[tm], aAddr[tm] + ks * 32);
        ldsm_x4(bq0, bAddr[0] + ks * 32);
        ldsm_x4(bq1, bAddr[1] + ks * 32);
        uint32_t bf[4][2];
        bf[0][0] = bq0[0]; bf[0][1] = bq0[1];
        bf[1][0] = bq0[2]; bf[1][1] = bq0[3];
        bf[2][0] = bq1[0]; bf[2][1] = bq1[1];
        bf[3][0] = bq1[2]; bf[3][1] = bq1[3];
#pragma unroll
        for (int tm = 0; tm < 4; tm++)
#pragma unroll
            for (int tn = 0; tn < 4; tn++)
                mma_bf16(acc[tm][tn], af[tm], bf[tn]);
    }

    __syncthreads();   // all warps done reading Q/K before union repurposed

    // ---- epilogue: exp + mask into smem half2 tile; per-row partial sums --
    const bool diag = (st == tt);
#pragma unroll
    for (int tm = 0; tm < 4; tm++)
#pragma unroll
        for (int rq = 0; rq < 2; rq++) {
            const int rloc = wm * 64 + tm * 16 + fr + rq * 8;
            const int t = t0 + rloc;
            float rsum = 0.f;
#pragma unroll
            for (int tn = 0; tn < 4; tn++) {
                const int s = s0 + wn * 32 + tn * 8 + 2 * fc;
                float e0 = __expf(acc[tm][tn][rq * 2 + 0] * SCALE);
                float e1 = __expf(acc[tm][tn][rq * 2 + 1] * SCALE);
                if (diag) {
                    if (s     > t) e0 = 0.f;
                    if (s + 1 > t) e1 = 0.f;
                }
                rsum += e0 + e1;
                __half2 h = __floats2half2_rn(e0, e1);
                sm.S[rloc][wn * 16 + tn * 4 + fc] = *(uint32_t*)&h;
            }
            rsum += __shfl_xor_sync(0xffffffffu, rsum, 1);
            rsum += __shfl_xor_sync(0xffffffffu, rsum, 2);
            if (fc == 0) rs[rloc][wn] = rsum;
        }
    __syncthreads();

    // g_RS first (independent of S-tile store; lets LSU overlap)
    if (tid < 128) {
        float v = rs[tid][0] + rs[tid][1] + rs[tid][2] + rs[tid][3];
        g_RS[((size_t)z * T + t0 + tid) * 16 + st] = v;
    }

    // ---- coalesced store: each pass writes 16 rows x 128 halves dense ----
    const int rr0 = tid >> 4;
    const int cw  = (tid & 15) * 4;
#pragma unroll
    for (int i = 0; i < 8; i++) {
        const int rr = rr0 + i * 16;
        uint4 v = *(const uint4*)&sm.S[rr][cw];
        *(uint4*)&Wp[(size_t)(t0 + rr) * T + s0 + cw * 2] = v;
    }
}

// ---------------------------------------------------------------------------
// Kernel 4: streaming mean-of-softmax. One block per (b,t), reverse order
// (longest rows scheduled first to pack the tail wave). 256 threads.
// ---------------------------------------------------------------------------
__global__ void __launch_bounds__(256)
softmax_mean_kernel(float* __restrict__ out_mean)
{
    const int row = (B * T - 1) - blockIdx.x;   // b*T + t, longest-first
    const int b = row >> 11;
    const int t = row & 2047;
    const int tid = threadIdx.x;

    const int nst = (t >> 7) + 1;
    const int L   = nst * 128;

    __shared__ float sinv[NH];
    if (tid < NH) {
        const float* p = g_RS + ((size_t)(tid * B + b) * T + t) * 16;
        float s = 0.f;
        for (int i = 0; i < nst; i++) s += p[i];
        sinv[tid] = (1.0f / NH) / s;
    }
    __syncthreads();

    const int c0 = tid * 8;
    float acc[8];
#pragma unroll
    for (int i = 0; i < 8; i++) acc[i] = 0.f;

    if (c0 < L) {
        const size_t rowoff = ((size_t)b * T + t) * T + c0;
#pragma unroll
        for (int n = 0; n < NH; n++) {
            const __half* p = g_Wh + (size_t)n * (B * (size_t)T * T) + rowoff;
            uint4 u = *(const uint4*)p;
            const float w = sinv[n];
            float2 f;
            f = __half22float2(*(__half2*)&u.x); acc[0] += f.x * w; acc[1] += f.y * w;
            f = __half22float2(*((__half2*)&u.x + 1)); acc[2] += f.x * w; acc[3] += f.y * w;
            f = __half22float2(*(__half2*)&u.z); acc[4] += f.x * w; acc[5] += f.y * w;
            f = __half22float2(*((__half2*)&u.z + 1)); acc[6] += f.x * w; acc[7] += f.y * w;
        }
    }

    float* mrow = out_mean + (size_t)row * T + c0;
    *(float4*)&mrow[0] = make_float4(acc[0], acc[1], acc[2], acc[3]);
    *(float4*)&mrow[4] = make_float4(acc[4], acc[5], acc[6], acc[7]);
}

// ---------------------------------------------------------------------------
// Kernel 5: AV via head-mean identity, 8 s-chunks. grid = (T/64, B, 8).
// ---------------------------------------------------------------------------
__global__ void av_kernel(const float* __restrict__ mean_w)
{
    const int t_tile = blockIdx.x;
    const int b      = blockIdx.y;
    const int chunk  = blockIdx.z;
    const int t0 = t_tile * 64;

    __shared__ float Ws[64][65];
    __shared__ float Vs[64][65];

    const int tx = threadIdx.x, ty = threadIdx.y;
    const int tid = ty * 16 + tx;

    float acc[4][4];
#pragma unroll
    for (int i = 0; i < 4; i++)
#pragma unroll
        for (int j = 0; j < 4; j++) acc[i][j] = 0.f;

    const int st_begin = chunk * 4;
    const int st_end   = min(chunk * 4 + 4, t_tile + 1);

    for (int st = st_begin; st < st_end; st++) {
        const int s0 = st * 64;
#pragma unroll
        for (int i = 0; i < 16; i++) {
            int idx = tid + i * 256;
            int r = idx >> 6, c = idx & 63;
            Ws[r][c] = mean_w[((size_t)b * T + t0 + r) * T + s0 + c];
            Vs[r][c] = g_V[((size_t)b * T + s0 + r) * D + c];
        }
        __syncthreads();
#pragma unroll 8
        for (int kk = 0; kk < 64; kk++) {
            float a[4], bb[4];
#pragma unroll
            for (int i = 0; i < 4; i++) a[i]  = Ws[ty * 4 + i][kk];
#pragma unroll
            for (int j = 0; j < 4; j++) bb[j] = Vs[kk][tx * 4 + j];
#pragma unroll
            for (int i = 0; i < 4; i++)
#pragma unroll
                for (int j = 0; j < 4; j++) acc[i][j] += a[i] * bb[j];
        }
        __syncthreads();
    }

    float* Cp = g_MHp + (size_t)chunk * B * T * D;
#pragma unroll
    for (int i = 0; i < 4; i++)
#pragma unroll
        for (int j = 0; j < 4; j++)
            Cp[((size_t)b * T + t0 + ty * 4 + i) * D + tx * 4 + j] = acc[i][j];
}

// mhsum: g_MH = sum of 8 AV partials (fixed order). grid = B*T*D/256.
__global__ void mhsum_kernel()
{
    const size_t i = (size_t)blockIdx.x * 256 + threadIdx.x;
    const size_t N = (size_t)B * T * D;
    float v = 0.f;
#pragma unroll
    for (int p = 0; p < 8; p++) v += g_MHp[p * N + i];
    g_MH[i] = v;
}

// ---------------------------------------------------------------------------
// Kernel 6: out = g_MH @ Wo + bo. grid = (H/64, B*T/64).
// ---------------------------------------------------------------------------
__global__ void out_kernel(const float* __restrict__ Wo,
                           const float* __restrict__ bo,
                           float* __restrict__ out)
{
    const int n0 = blockIdx.x * 64;
    const int m0 = blockIdx.y * 64;

    __shared__ float As[64][65];
    __shared__ float Bs[64][65];

    const int tx = threadIdx.x, ty = threadIdx.y;
    const int tid = ty * 16 + tx;

#pragma unroll
    for (int i = 0; i < 16; i++) {
        int idx = tid + i * 256;
        int r = idx >> 6, c = idx & 63;
        As[r][c] = g_MH[(size_t)(m0 + r) * D + c];
        Bs[r][c] = Wo[(size_t)r * H + n0 + c];
    }
    __syncthreads();

    float acc[4][4];
#pragma unroll
    for (int i = 0; i < 4; i++)
#pragma unroll
        for (int j = 0; j < 4; j++) acc[i][j] = 0.f;

#pragma unroll 8
    for (int kk = 0; kk < 64; kk++) {
        float a[4], bb[4];
#pragma unroll
        for (int i = 0; i < 4; i++) a[i]  = As[ty * 4 + i][kk];
#pragma unroll
        for (int j = 0; j < 4; j++) bb[j] = Bs[kk][tx * 4 + j];
#pragma unroll
        for (int i = 0; i < 4; i++)
#pragma unroll
            for (int j = 0; j < 4; j++) acc[i][j] += a[i] * bb[j];
    }

#pragma unroll
    for (int i = 0; i < 4; i++)
#pragma unroll
        for (int j = 0; j < 4; j++)
            out[(size_t)(m0 + ty * 4 + i) * H + n0 + tx * 4 + j] =
                acc[i][j] + bo[n0 + tx * 4 + j];
}

// ---------------------------------------------------------------------------
extern "C" void kernel_launch(void* const* d_in, const int* in_sizes, int n_in,
                              void* d_out, int out_size)
{
    const float* x  = (const float*)d_in[0];
    const float* Wq = (const float*)d_in[1];
    const float* bq = (const float*)d_in[2];
    const float* Wk = (const float*)d_in[3];
    const float* bk = (const float*)d_in[4];
    const float* Wv = (const float*)d_in[5];
    const float* bv = (const float*)d_in[6];
    const float* Wo = (const float*)d_in[7];
    const float* bo = (const float*)d_in[8];

    float* out      = (float*)d_out;                 // [B,T,H]
    float* mean_out = out + (size_t)B * T * H;       // [B,T,T]

    dim3 blk16(16, 16);

    qkproj_bf16        <<<dim3(H / 128, (B * T) / 128, 2), 256>>>(x, Wq, bq, Wk, bk);
    vproj_kernel       <<<dim3((B * T) / 64, 4), blk16>>>(x, Wv);
    vsum_kernel        <<<(B * T * D) / 256, 256>>>(bv);
    scores_bf16        <<<dim3(T / 128, T / 128, NH * B), 256>>>();
    softmax_mean_kernel<<<B * T, 256>>>(mean_out);
    av_kernel          <<<dim3(T / 64, B, 8), blk16>>>(mean_out);
    mhsum_kernel       <<<(B * T * D) / 256, 256>>>();
    out_kernel         <<<dim3(H / 64, (B * T) / 64), blk16>>>(Wo, bo, out);
}